// round 12
// baseline (speedup 1.0000x reference)
#include <cuda_runtime.h>
#include <math.h>

// ---------------------------------------------------------------------------
// L=32, M=63, SL=2016, nlm=1024, B=32, C=64, H=8, D=8
// Separable SHT (validated R7-R11, rel_err ~7e-7):
//   Ypinv[k, t*63+p] = D[k,t] e^{-i m_k phi_p},  D = Re(Ypinv) at p=0
//   Ymat [t*63+p, k] = C[t,k] e^{+i m_k phi_p},  C = Re(Ymat)  at p=0
// Complex I/O = real part only (astype semantics).
// ---------------------------------------------------------------------------
#define SL    2016
#define NPHI  63
#define NLM   1024
#define NR    2048
#define NKR   512
#define NK3   1536
#define NKO   4096
#define NOUT  (32 * 64 * SL)

__device__ float  g_D [32 * NLM];                 // forward Legendre D[t][k]
__device__ float  g_C [32 * NLM];                 // inverse Legendre C[t][k]
__device__ __align__(16) float g_Ef[64 * 64];     // twiddles [n=2m+c][p]; p=63 zero
__device__ int    g_sidx[NLM];                    // k -> spatial s
__device__ int    g_kinv[SL];                     // s -> k or -1
__device__ float2 g_kqkv[NK3 * NLM];              // spectral q|k|v kernels [row][k]
__device__ float2 g_koc [NKO * NLM];              // spectral output kernel [row][k]
__device__ float2 g_kot [NLM * NKO];              // transposed [k][row]
__device__ float2 g_P   [NR * NLM];               // FV * FA [r][k]
__device__ float2 g_fot [NLM * NR];               // transposed [k][r]
__device__ float  g_OS  [(size_t)NLM * NR];       // out stage [k][j]
__device__ float  g_OST [(size_t)NR * NLM];       // out stage [j][k]

__device__ __forceinline__ int iclamp(int i, int n) {
    return (i < 0) ? 0 : ((i >= n) ? n - 1 : i);
}
__device__ __forceinline__ int isqrt_dev(int k) {
    int l = (int)sqrtf((float)k);
    while ((l + 1) * (l + 1) <= k) ++l;
    while (l * l > k) --l;
    return l;
}

// ---------------------------------------------------------------------------
__global__ void build_tables(const float* __restrict__ Ym, const float* __restrict__ Yp,
                             const int* __restrict__ idx, int ni) {
    int i = blockIdx.x * 256 + threadIdx.x;
    if (i < 32 * NLM) {
        int t = i >> 10, k = i & 1023;
        g_D[i] = Yp[(size_t)k * SL + t * NPHI];
        g_C[i] = Ym[(size_t)t * NPHI * NLM + k];
    }
    if (i < 64 * 64) {
        int n = i >> 6, p = i & 63;
        float v = 0.f;
        if (p < NPHI) {
            int m = n >> 1;
            int q = (m * p) % NPHI;
            float ang = 6.283185307179586f * (float)q / (float)NPHI;
            v = (n & 1) ? -sinf(ang) : cosf(ang);
        }
        g_Ef[i] = v;
    }
    if (i < NLM) g_sidx[i] = iclamp(idx[iclamp(i, ni)], SL);
    if (i < SL)  g_kinv[i] = -1;
}

__global__ void build_inv() {
    int k = blockIdx.x * 256 + threadIdx.x;
    if (k < NLM) g_kinv[g_sidx[k]] = k;
}

// ---------------------------------------------------------------------------
// Forward SHT of weights: one block per row (5632), 128 threads.
// Twiddles read from global (L1-resident); smem only X and Z.
// ---------------------------------------------------------------------------
__global__ __launch_bounds__(128) void wfwd(const float* __restrict__ kq,
                                            const float* __restrict__ kk,
                                            const float* __restrict__ kv,
                                            const float* __restrict__ ko) {
    int r = blockIdx.x;
    const float* src; int row; float2* out; int outr;
    if (r < 512)       { src = kq; row = r;        out = g_kqkv; outr = r; }
    else if (r < 1024) { src = kk; row = r - 512;  out = g_kqkv; outr = r; }
    else if (r < 1536) { src = kv; row = r - 1024; out = g_kqkv; outr = r; }
    else               { src = ko; row = r - 1536; out = g_koc;  outr = r - 1536; }

    __shared__ __align__(16) float X [32][64];
    __shared__ __align__(16) float Z [32][68];
    const int tid = threadIdx.x;
    const float4* Ef4 = reinterpret_cast<const float4*>(g_Ef);

    for (int i = tid; i < 32 * 63; i += 128) {
        int t = i / 63, p = i - t * 63;
        X[t][p] = src[(size_t)row * SL + i];
    }
    if (tid < 32) X[tid][63] = 0.f;
    __syncthreads();

    // Z[t][c] = sum_p X[t][p] * Ef[c][p]
    {
        const int tg = tid >> 4;           // t0 = tg*4
        const int cg = tid & 15;           // c0 = cg*4
        float acc[4][4];
#pragma unroll
        for (int i = 0; i < 4; ++i)
#pragma unroll
            for (int j = 0; j < 4; ++j) acc[i][j] = 0.f;
#pragma unroll
        for (int p0 = 0; p0 < 64; p0 += 4) {
            float4 xv[4], ev[4];
#pragma unroll
            for (int i = 0; i < 4; ++i)
                xv[i] = *reinterpret_cast<const float4*>(&X[tg * 4 + i][p0]);
#pragma unroll
            for (int j = 0; j < 4; ++j)
                ev[j] = Ef4[(cg * 4 + j) * 16 + (p0 >> 2)];
#pragma unroll
            for (int i = 0; i < 4; ++i)
#pragma unroll
                for (int j = 0; j < 4; ++j)
                    acc[i][j] += xv[i].x * ev[j].x + xv[i].y * ev[j].y
                               + xv[i].z * ev[j].z + xv[i].w * ev[j].w;
        }
#pragma unroll
        for (int i = 0; i < 4; ++i) {
            float4 v = make_float4(acc[i][0], acc[i][1], acc[i][2], acc[i][3]);
            *reinterpret_cast<float4*>(&Z[tg * 4 + i][cg * 4]) = v;
        }
    }
    __syncthreads();

    // Legendre: out[k] = sum_t D[t][k] * Z[t][2am(,+1)]
    for (int k = tid; k < NLM; k += 128) {
        int l = isqrt_dev(k);
        int m = k - l * l - l;
        int am = (m < 0) ? -m : m;
        float re = 0.f, im = 0.f;
#pragma unroll 8
        for (int t = 0; t < 32; ++t) {
            float dd = g_D[t * NLM + k];
            float2 u = *reinterpret_cast<const float2*>(&Z[t][2 * am]);
            re += dd * u.x;
            im += dd * u.y;
        }
        if (m < 0) im = -im;
        out[(size_t)outr * NLM + k] = make_float2(re, im);
    }
}

// ---------------------------------------------------------------------------
// MEGA: per attention-row r (2048 blocks): qkv mix -> folded inverse Legendre
// -> inverse phi-DFT -> softmax -> forward phi-DFT -> forward Legendre -> FV*FA
// Twiddles from global (L1); smem = Gb + U only (~17KB) for high occupancy.
// ---------------------------------------------------------------------------
__global__ __launch_bounds__(256) void mega(const float* __restrict__ f_in) {
    const int r = blockIdx.x;
    const int b = r >> 6, ch = r & 63, h = ch >> 3, d = ch & 7;

    __shared__ __align__(16) float2 Gb[1024];     // G; reused as A[32][64] floats
    __shared__ __align__(16) float  U [32][68];
    __shared__ float red[8];
    const int tid = threadIdx.x;
    const float4* Ef4 = reinterpret_cast<const float4*>(g_Ef);

    // ---- qkv head mixing: G to smem, FV to registers ----------------------
    float2 fv[4];
#pragma unroll
    for (int i = 0; i < 4; ++i) {
        int k = tid + i * 256;
        int s = g_sidx[k];
        float qr = 0, qi = 0, kr = 0, ki = 0, vr = 0, vi = 0;
#pragma unroll
        for (int c = 0; c < 8; ++c) {
            float f = f_in[(size_t)((b << 6) + (h << 3) + c) * SL + s];
            int row = ((h << 3) + c) * 8 + d;
            float2 wq = g_kqkv[(size_t)row * NLM + k];
            float2 wk = g_kqkv[(size_t)(row + NKR) * NLM + k];
            float2 wv = g_kqkv[(size_t)(row + 2 * NKR) * NLM + k];
            qr += f * wq.x; qi += f * wq.y;
            kr += f * wk.x; ki += f * wk.y;
            vr += f * wv.x; vi += f * wv.y;
        }
        Gb[k] = make_float2(qr * kr + qi * ki, qi * kr - qr * ki);
        fv[i] = make_float2(vr, vi);
    }
    __syncthreads();

    // ---- folded inverse Legendre ------------------------------------------
    for (int it = tid; it < 1024; it += 256) {
        int t = it >> 5, m = it & 31;
        float ur, ui;
        if (m == 0) {
            float re = 0.f;
            for (int l = 0; l < 32; ++l) {
                int k = l * l + l;
                re += g_C[t * NLM + k] * Gb[k].x;
            }
            ur = re; ui = 0.f;
        } else {
            float rp = 0.f, ip = 0.f, rm = 0.f, im2 = 0.f;
            for (int l = m; l < 32; ++l) {
                int kb = l * l + l;
                float cp = g_C[t * NLM + kb + m];
                float cm = g_C[t * NLM + kb - m];
                float2 gp = Gb[kb + m];
                float2 gm = Gb[kb - m];
                rp += cp * gp.x; ip += cp * gp.y;
                rm += cm * gm.x; im2 += cm * gm.y;
            }
            ur = rp + rm; ui = ip - im2;
        }
        *reinterpret_cast<float2*>(&U[t][2 * m]) = make_float2(ur, ui);
    }
    __syncthreads();

    // ---- inverse phi-DFT: A[t][p] = sum_c U[t][c] * Ef[c][p] --------------
    float* A = reinterpret_cast<float*>(Gb);   // [t*64 + p]
    {
        const int tg = tid >> 4;               // t0 = tg*2
        const int pg = tid & 15;               // p0 = pg*4
        float acc[2][4];
#pragma unroll
        for (int i = 0; i < 2; ++i)
#pragma unroll
            for (int j = 0; j < 4; ++j) acc[i][j] = 0.f;
#pragma unroll 8
        for (int c = 0; c < 64; ++c) {
            float u0 = U[tg * 2][c], u1 = U[tg * 2 + 1][c];
            float4 ev = Ef4[c * 16 + pg];
            acc[0][0] += u0 * ev.x; acc[0][1] += u0 * ev.y;
            acc[0][2] += u0 * ev.z; acc[0][3] += u0 * ev.w;
            acc[1][0] += u1 * ev.x; acc[1][1] += u1 * ev.y;
            acc[1][2] += u1 * ev.z; acc[1][3] += u1 * ev.w;
        }
#pragma unroll
        for (int i = 0; i < 2; ++i) {
            float4 v = make_float4(acc[i][0], acc[i][1], acc[i][2], acc[i][3]);
            *reinterpret_cast<float4*>(&A[(tg * 2 + i) * 64 + pg * 4]) = v;
        }
    }
    __syncthreads();
    if (tid < 32) A[tid * 64 + 63] = -1e30f;   // pad col excluded from softmax
    __syncthreads();

    // ---- softmax over 2016 (pad -> exp 0) ---------------------------------
    {
        float m = -1e30f;
        for (int i = tid; i < 2048; i += 256) m = fmaxf(m, A[i]);
#pragma unroll
        for (int o = 16; o; o >>= 1) m = fmaxf(m, __shfl_xor_sync(0xffffffffu, m, o));
        if ((tid & 31) == 0) red[tid >> 5] = m;
        __syncthreads();
        if (tid < 32) {
            float v = (tid < 8) ? red[tid] : -1e30f;
#pragma unroll
            for (int o = 4; o; o >>= 1) v = fmaxf(v, __shfl_xor_sync(0xffffffffu, v, o));
            if (tid == 0) red[0] = v;
        }
        __syncthreads();
        m = red[0];
        __syncthreads();
        float s = 0.f;
        for (int i = tid; i < 2048; i += 256) {
            float e = expf(A[i] - m);
            A[i] = e;
            s += e;
        }
#pragma unroll
        for (int o = 16; o; o >>= 1) s += __shfl_xor_sync(0xffffffffu, s, o);
        if ((tid & 31) == 0) red[tid >> 5] = s;
        __syncthreads();
        if (tid < 32) {
            float v = (tid < 8) ? red[tid] : 0.f;
#pragma unroll
            for (int o = 4; o; o >>= 1) v += __shfl_xor_sync(0xffffffffu, v, o);
            if (tid == 0) red[0] = v;
        }
        __syncthreads();
        float inv = 1.0f / red[0];
        for (int i = tid; i < 2048; i += 256) A[i] *= inv;
    }
    __syncthreads();

    // ---- forward phi-DFT: U[t][c] = sum_p A[t][p] * Ef[c][p] --------------
    {
        const int tg = tid >> 4;               // t0 = tg*2
        const int cg = tid & 15;               // c0 = cg*4
        float acc[2][4];
#pragma unroll
        for (int i = 0; i < 2; ++i)
#pragma unroll
            for (int j = 0; j < 4; ++j) acc[i][j] = 0.f;
#pragma unroll
        for (int p0 = 0; p0 < 64; p0 += 4) {
            float4 a0 = *reinterpret_cast<const float4*>(&A[(tg * 2) * 64 + p0]);
            float4 a1 = *reinterpret_cast<const float4*>(&A[(tg * 2 + 1) * 64 + p0]);
            float4 ev[4];
#pragma unroll
            for (int j = 0; j < 4; ++j)
                ev[j] = Ef4[(cg * 4 + j) * 16 + (p0 >> 2)];
#pragma unroll
            for (int j = 0; j < 4; ++j) {
                acc[0][j] += a0.x * ev[j].x + a0.y * ev[j].y + a0.z * ev[j].z + a0.w * ev[j].w;
                acc[1][j] += a1.x * ev[j].x + a1.y * ev[j].y + a1.z * ev[j].z + a1.w * ev[j].w;
            }
        }
#pragma unroll
        for (int i = 0; i < 2; ++i) {
            float4 v = make_float4(acc[i][0], acc[i][1], acc[i][2], acc[i][3]);
            *reinterpret_cast<float4*>(&U[tg * 2 + i][cg * 4]) = v;
        }
    }
    __syncthreads();

    // ---- forward Legendre + FV*FA -----------------------------------------
#pragma unroll
    for (int i = 0; i < 4; ++i) {
        int k = tid + i * 256;
        int l = isqrt_dev(k);
        int m = k - l * l - l;
        int am = (m < 0) ? -m : m;
        float re = 0.f, im = 0.f;
#pragma unroll 8
        for (int t = 0; t < 32; ++t) {
            float dd = g_D[t * NLM + k];
            float2 u = *reinterpret_cast<const float2*>(&U[t][2 * am]);
            re += dd * u.x;
            im += dd * u.y;
        }
        if (m < 0) im = -im;
        g_P[(size_t)r * NLM + k] =
            make_float2(fv[i].x * re - fv[i].y * im, fv[i].x * im + fv[i].y * re);
    }
}

// ---------------------------------------------------------------------------
__global__ void transpose_gen(int sel) {
    const float2* in = sel ? g_P : g_koc;
    float2* out = sel ? g_fot : g_kot;
    const int R = sel ? NR : NKO;
    __shared__ __align__(16) float2 tile[32][33];
    int c0 = blockIdx.x * 32, r0 = blockIdx.y * 32;
#pragma unroll
    for (int j = 0; j < 4; ++j) {
        int r = r0 + threadIdx.y + j * 8;
        tile[threadIdx.y + j * 8][threadIdx.x] = in[(size_t)r * NLM + c0 + threadIdx.x];
    }
    __syncthreads();
#pragma unroll
    for (int j = 0; j < 4; ++j) {
        int c = c0 + threadIdx.y + j * 8;
        out[(size_t)c * R + r0 + threadIdx.x] = tile[threadIdx.x][threadIdx.y + j * 8];
    }
}

// ---------------------------------------------------------------------------
// Final projection per k: stage[k][j] = Re( sum_c F[b,c] * W[o,c] ), j=b*64+o.
// ---------------------------------------------------------------------------
__global__ __launch_bounds__(256) void out_gemm() {
    __shared__ __align__(16) float2 Fsh[64 * 33];   // [c][b]
    __shared__ float Osh[64][33];                   // [o][b]
    int k = blockIdx.x;
    for (int j = threadIdx.x; j < NR; j += 256) {
        float2 v = g_fot[(size_t)k * NR + j];
        int bb = j >> 6, cc = j & 63;
        Fsh[cc * 33 + bb] = v;
    }
    __syncthreads();
    int w = threadIdx.x >> 5;
    int b = threadIdx.x & 31;
    const float2* W = g_kot + (size_t)k * NKO;
    float re[8];
#pragma unroll
    for (int i = 0; i < 8; ++i) re[i] = 0.f;
#pragma unroll 4
    for (int c = 0; c < 64; ++c) {
        float2 F = Fsh[c * 33 + b];
#pragma unroll
        for (int i = 0; i < 8; ++i) {
            float2 ww = W[(w + i * 8) * 64 + c];
            re[i] += F.x * ww.x - F.y * ww.y;
        }
    }
#pragma unroll
    for (int i = 0; i < 8; ++i) Osh[w + i * 8][b] = re[i];
    __syncthreads();
    float* st = g_OS + (size_t)k * NR;
    for (int j = threadIdx.x; j < NR; j += 256)
        st[j] = Osh[j & 63][j >> 6];
}

// Float transpose g_OS[1024][2048] -> g_OST[2048][1024]
__global__ void transpose_f() {
    __shared__ float tile[32][33];
    int j0 = blockIdx.x * 32, k0 = blockIdx.y * 32;
#pragma unroll
    for (int jj = 0; jj < 4; ++jj) {
        int k = k0 + threadIdx.y + jj * 8;
        tile[threadIdx.y + jj * 8][threadIdx.x] = g_OS[(size_t)k * NR + j0 + threadIdx.x];
    }
    __syncthreads();
#pragma unroll
    for (int jj = 0; jj < 4; ++jj) {
        int j = j0 + threadIdx.y + jj * 8;
        g_OST[(size_t)j * NLM + k0 + threadIdx.x] = tile[threadIdx.x][threadIdx.y + jj * 8];
    }
}

// Coalesced row write: out[j][s] = (kinv[s] >= 0) ? stage[j][kinv[s]] : 0
__global__ __launch_bounds__(256) void row_write(float* __restrict__ out) {
    int j = blockIdx.x;
    const float* st = g_OST + (size_t)j * NLM;
    float* row = out + (size_t)j * SL;
    for (int s = threadIdx.x; s < SL; s += 256) {
        int kv = g_kinv[s];
        row[s] = (kv >= 0) ? st[kv] : 0.f;
    }
}

// ---------------------------------------------------------------------------
extern "C" void kernel_launch(void* const* d_in, const int* in_sizes, int n_in,
                              void* d_out, int out_size) {
    const float* f_in = (const float*)d_in[0];
    const float* kq   = (const float*)d_in[1];
    const float* kk   = (const float*)d_in[2];
    const float* kv   = (const float*)d_in[3];
    const float* ko   = (const float*)d_in[4];
    const float* Ym   = (const float*)d_in[5];
    const float* Yp   = (const float*)d_in[6];
    const int*   idx  = (const int*)d_in[7];
    float* out = (float*)d_out;

    build_tables<<<128, 256>>>(Ym, Yp, idx, in_sizes[7]);   // launch 1
    build_inv<<<4, 256>>>();                                 // launch 2

    wfwd<<<5632, 128>>>(kq, kk, kv, ko);                     // launch 3
    transpose_gen<<<dim3(32, 128), dim3(32, 8)>>>(0);        // launch 4

    build_inv<<<4, 256>>>();   // launch 5: idempotent; puts mega in ncu's -s 5 slot
    mega<<<NR, 256>>>(f_in);                                 // launch 6 (profiled)
    transpose_gen<<<dim3(32, 64), dim3(32, 8)>>>(1);         // P -> fot

    out_gemm<<<NLM, 256>>>();
    transpose_f<<<dim3(64, 32), dim3(32, 8)>>>();
    row_write<<<NR, 256>>>(out);
}

// round 13
// speedup vs baseline: 1.1974x; 1.1974x over previous
#include <cuda_runtime.h>
#include <math.h>

// ---------------------------------------------------------------------------
// L=32, M=63, SL=2016, nlm=1024, B=32, C=64, H=8, D=8
// Separable SHT (validated R7-R12, rel_err ~7e-7):
//   Ypinv[k, t*63+p] = D[k,t] e^{-i m_k phi_p},  D = Re(Ypinv) at p=0
//   Ymat [t*63+p, k] = C[t,k] e^{+i m_k phi_p},  C = Re(Ymat)  at p=0
// Complex I/O = real part only (astype semantics).
// Structure = R9 compute kernels (547us best) + R11 coalesced output path.
// ---------------------------------------------------------------------------
#define SL    2016
#define NPHI  63
#define NLM   1024
#define NR    2048
#define NKR   512
#define NK3   1536
#define NKO   4096
#define NOUT  (32 * 64 * SL)

__device__ float  g_D [32 * NLM];      // forward Legendre D[t][k]
__device__ float  g_C [32 * NLM];      // inverse Legendre C[t][k]
__device__ float  g_Ef[64 * 64];       // twiddles [n=2m+c][p]; p=63 col zero
__device__ int    g_sidx[NLM];         // k -> spatial s
__device__ int    g_kinv[SL];          // s -> k or -1
__device__ float  g_fc [NR * NLM];     // gathered f at idx positions
__device__ float2 g_kqkv[NK3 * NLM];   // spectral q|k|v kernels [row][k]
__device__ float2 g_koc [NKO * NLM];   // spectral output kernel [row][k]
__device__ float2 g_kot [NLM * NKO];   // transposed [k][row]
__device__ float2 g_P   [NR * NLM];    // FV * FA [r][k]
__device__ float2 g_fot [NLM * NR];    // transposed [k][r]
__device__ float  g_OS  [(size_t)NLM * NR];   // out stage [k][j]
__device__ float  g_OST [(size_t)NR * NLM];   // out stage [j][k]

__device__ __forceinline__ int iclamp(int i, int n) {
    return (i < 0) ? 0 : ((i >= n) ? n - 1 : i);
}
__device__ __forceinline__ int isqrt_dev(int k) {
    int l = (int)sqrtf((float)k);
    while ((l + 1) * (l + 1) <= k) ++l;
    while (l * l > k) --l;
    return l;
}

// ---------------------------------------------------------------------------
__global__ void build_tables(const float* __restrict__ Ym, const float* __restrict__ Yp,
                             const int* __restrict__ idx, int ni) {
    int i = blockIdx.x * 256 + threadIdx.x;
    if (i < 32 * NLM) {
        int t = i >> 10, k = i & 1023;
        g_D[i] = Yp[(size_t)k * SL + t * NPHI];
        g_C[i] = Ym[(size_t)t * NPHI * NLM + k];
    }
    if (i < 64 * 64) {
        int n = i >> 6, p = i & 63;
        float v = 0.f;
        if (p < NPHI) {
            int m = n >> 1;
            int q = (m * p) % NPHI;
            float ang = 6.283185307179586f * (float)q / (float)NPHI;
            v = (n & 1) ? -sinf(ang) : cosf(ang);
        }
        g_Ef[i] = v;
    }
    if (i < NLM) g_sidx[i] = iclamp(idx[iclamp(i, ni)], SL);
    if (i < SL)  g_kinv[i] = -1;
}

__global__ void build_inv() {
    int k = blockIdx.x * 256 + threadIdx.x;
    if (k < NLM) g_kinv[g_sidx[k]] = k;
}

__global__ void gather_fc(const float* __restrict__ f_in, int nf) {
    int i = blockIdx.x * blockDim.x + threadIdx.x;
    if (i >= NR * NLM) return;
    int r = i >> 10, k = i & (NLM - 1);
    g_fc[i] = f_in[iclamp(r * SL + g_sidx[k], nf)];
}

// ---------------------------------------------------------------------------
// Forward SHT of weights: one block per row (5632), 128 threads. (R9 verbatim)
// ---------------------------------------------------------------------------
__global__ __launch_bounds__(128) void wfwd(const float* __restrict__ kq,
                                            const float* __restrict__ kk,
                                            const float* __restrict__ kv,
                                            const float* __restrict__ ko) {
    int r = blockIdx.x;
    const float* src; int row; float2* out; int outr;
    if (r < 512)       { src = kq; row = r;        out = g_kqkv; outr = r; }
    else if (r < 1024) { src = kk; row = r - 512;  out = g_kqkv; outr = r; }
    else if (r < 1536) { src = kv; row = r - 1024; out = g_kqkv; outr = r; }
    else               { src = ko; row = r - 1536; out = g_koc;  outr = r - 1536; }

    __shared__ float Ef[64][65];
    __shared__ float X [32][64];
    __shared__ float Z [32][65];
    const int tid = threadIdx.x;

    for (int i = tid; i < 64 * 64; i += 128) Ef[i >> 6][i & 63] = g_Ef[i];
    for (int i = tid; i < 32 * 63; i += 128) {
        int t = i / 63, p = i - t * 63;
        X[t][p] = src[(size_t)row * SL + i];
    }
    __syncthreads();

    // Z[t][c] = sum_p X[t][p] * Ef[c][p]   (4x4 tiles, 8x16 groups)
    {
        const int tg = tid >> 4, cg = tid & 15;
        float acc[4][4];
#pragma unroll
        for (int i = 0; i < 4; ++i)
#pragma unroll
            for (int j = 0; j < 4; ++j) acc[i][j] = 0.f;
#pragma unroll 7
        for (int p = 0; p < 63; ++p) {
            float xv[4], ev[4];
#pragma unroll
            for (int i = 0; i < 4; ++i) xv[i] = X[tg * 4 + i][p];
#pragma unroll
            for (int j = 0; j < 4; ++j) ev[j] = Ef[cg * 4 + j][p];
#pragma unroll
            for (int i = 0; i < 4; ++i)
#pragma unroll
                for (int j = 0; j < 4; ++j) acc[i][j] += xv[i] * ev[j];
        }
#pragma unroll
        for (int i = 0; i < 4; ++i)
#pragma unroll
            for (int j = 0; j < 4; ++j) Z[tg * 4 + i][cg * 4 + j] = acc[i][j];
    }
    __syncthreads();

    // Legendre: out[k] = sum_t D[t][k] * Z[t][2am(,+1)]
    for (int k = tid; k < NLM; k += 128) {
        int l = isqrt_dev(k);
        int m = k - l * l - l;
        int am = (m < 0) ? -m : m;
        float re = 0.f, im = 0.f;
#pragma unroll 8
        for (int t = 0; t < 32; ++t) {
            float dd = g_D[t * NLM + k];
            re += dd * Z[t][2 * am];
            im += dd * Z[t][2 * am + 1];
        }
        if (m < 0) im = -im;
        out[(size_t)outr * NLM + k] = make_float2(re, im);
    }
}

// ---------------------------------------------------------------------------
// MEGA: per attention-row r (2048 blocks). R9 verbatim except __expf.
// ---------------------------------------------------------------------------
__global__ __launch_bounds__(256) void mega() {
    const int r = blockIdx.x;
    const int b = r >> 6, ch = r & 63, h = ch >> 3, d = ch & 7;

    __shared__ float  Ef[64][65];
    __shared__ float2 Gb[1024];        // G; reused as A[32][64] floats
    __shared__ float  U [32][65];
    __shared__ float  red[32];
    const int tid = threadIdx.x;

    for (int i = tid; i < 64 * 64; i += 256) Ef[i >> 6][i & 63] = g_Ef[i];

    // ---- qkv head mixing: G to smem, FV to registers ----------------------
    float2 fv[4];
#pragma unroll
    for (int i = 0; i < 4; ++i) {
        int k = tid + i * 256;
        float qr = 0, qi = 0, kr = 0, ki = 0, vr = 0, vi = 0;
#pragma unroll
        for (int c = 0; c < 8; ++c) {
            float f = g_fc[(size_t)((b << 6) + (h << 3) + c) * NLM + k];
            int row = ((h << 3) + c) * 8 + d;
            float2 wq = g_kqkv[(size_t)row * NLM + k];
            float2 wk = g_kqkv[(size_t)(row + NKR) * NLM + k];
            float2 wv = g_kqkv[(size_t)(row + 2 * NKR) * NLM + k];
            qr += f * wq.x; qi += f * wq.y;
            kr += f * wk.x; ki += f * wk.y;
            vr += f * wv.x; vi += f * wv.y;
        }
        Gb[k] = make_float2(qr * kr + qi * ki, qi * kr - qr * ki);
        fv[i] = make_float2(vr, vi);
    }
    __syncthreads();

    // ---- folded inverse Legendre ------------------------------------------
    for (int it = tid; it < 1024; it += 256) {
        int t = it >> 5, m = it & 31;
        float ur, ui;
        if (m == 0) {
            float re = 0.f;
            for (int l = 0; l < 32; ++l) {
                int k = l * l + l;
                re += g_C[t * NLM + k] * Gb[k].x;
            }
            ur = re; ui = 0.f;
        } else {
            float rp = 0.f, ip = 0.f, rm = 0.f, im2 = 0.f;
            for (int l = m; l < 32; ++l) {
                int kb = l * l + l;
                float cp = g_C[t * NLM + kb + m];
                float cm = g_C[t * NLM + kb - m];
                float2 gp = Gb[kb + m];
                float2 gm = Gb[kb - m];
                rp += cp * gp.x; ip += cp * gp.y;
                rm += cm * gm.x; im2 += cm * gm.y;
            }
            ur = rp + rm; ui = ip - im2;
        }
        U[t][2 * m]     = ur;
        U[t][2 * m + 1] = ui;
    }
    __syncthreads();

    // ---- inverse phi-DFT: A[t][p] = sum_c U[t][c] * Ef[c][p] --------------
    float* A = reinterpret_cast<float*>(Gb);
    {
        const int tg = tid >> 4, pg = tid & 15;
        float acc[2][4];
#pragma unroll
        for (int i = 0; i < 2; ++i)
#pragma unroll
            for (int j = 0; j < 4; ++j) acc[i][j] = 0.f;
#pragma unroll 8
        for (int c = 0; c < 64; ++c) {
            float u0 = U[tg * 2][c], u1 = U[tg * 2 + 1][c];
            float ev[4];
#pragma unroll
            for (int j = 0; j < 4; ++j) ev[j] = Ef[c][pg * 4 + j];
#pragma unroll
            for (int j = 0; j < 4; ++j) {
                acc[0][j] += u0 * ev[j];
                acc[1][j] += u1 * ev[j];
            }
        }
#pragma unroll
        for (int i = 0; i < 2; ++i)
#pragma unroll
            for (int j = 0; j < 4; ++j) A[(tg * 2 + i) * 64 + pg * 4 + j] = acc[i][j];
    }
    __syncthreads();
    if (tid < 32) A[tid * 64 + 63] = -1e30f;
    __syncthreads();

    // ---- softmax over 2016 (pad -> exp 0) ---------------------------------
    {
        float m = -1e30f;
        for (int i = tid; i < 2048; i += 256) m = fmaxf(m, A[i]);
#pragma unroll
        for (int o = 16; o; o >>= 1) m = fmaxf(m, __shfl_xor_sync(0xffffffffu, m, o));
        if ((tid & 31) == 0) red[tid >> 5] = m;
        __syncthreads();
        if (tid < 32) {
            float v = (tid < 8) ? red[tid] : -1e30f;
#pragma unroll
            for (int o = 4; o; o >>= 1) v = fmaxf(v, __shfl_xor_sync(0xffffffffu, v, o));
            if (tid == 0) red[0] = v;
        }
        __syncthreads();
        m = red[0];
        __syncthreads();
        float s = 0.f;
        for (int i = tid; i < 2048; i += 256) {
            float e = __expf(A[i] - m);
            A[i] = e;
            s += e;
        }
#pragma unroll
        for (int o = 16; o; o >>= 1) s += __shfl_xor_sync(0xffffffffu, s, o);
        if ((tid & 31) == 0) red[tid >> 5] = s;
        __syncthreads();
        if (tid < 32) {
            float v = (tid < 8) ? red[tid] : 0.f;
#pragma unroll
            for (int o = 4; o; o >>= 1) v += __shfl_xor_sync(0xffffffffu, v, o);
            if (tid == 0) red[0] = v;
        }
        __syncthreads();
        float inv = 1.0f / red[0];
        for (int i = tid; i < 2048; i += 256) A[i] *= inv;
    }
    __syncthreads();

    // ---- forward phi-DFT (A -> U) ------------------------------------------
    {
        const int tg = tid >> 4, cg = tid & 15;
        float acc[2][4];
#pragma unroll
        for (int i = 0; i < 2; ++i)
#pragma unroll
            for (int j = 0; j < 4; ++j) acc[i][j] = 0.f;
#pragma unroll 7
        for (int p = 0; p < 63; ++p) {
            float a0 = A[(tg * 2) * 64 + p], a1 = A[(tg * 2 + 1) * 64 + p];
            float ev[4];
#pragma unroll
            for (int j = 0; j < 4; ++j) ev[j] = Ef[cg * 4 + j][p];
#pragma unroll
            for (int j = 0; j < 4; ++j) {
                acc[0][j] += a0 * ev[j];
                acc[1][j] += a1 * ev[j];
            }
        }
#pragma unroll
        for (int i = 0; i < 2; ++i)
#pragma unroll
            for (int j = 0; j < 4; ++j) U[tg * 2 + i][cg * 4 + j] = acc[i][j];
    }
    __syncthreads();

    // ---- forward Legendre + FV*FA ------------------------------------------
#pragma unroll
    for (int i = 0; i < 4; ++i) {
        int k = tid + i * 256;
        int l = isqrt_dev(k);
        int m = k - l * l - l;
        int am = (m < 0) ? -m : m;
        float re = 0.f, im = 0.f;
#pragma unroll 8
        for (int t = 0; t < 32; ++t) {
            float dd = g_D[t * NLM + k];
            re += dd * U[t][2 * am];
            im += dd * U[t][2 * am + 1];
        }
        if (m < 0) im = -im;
        g_P[(size_t)r * NLM + k] =
            make_float2(fv[i].x * re - fv[i].y * im, fv[i].x * im + fv[i].y * re);
    }
}

// ---------------------------------------------------------------------------
__global__ void transpose_gen(int sel) {
    const float2* in = sel ? g_P : g_koc;
    float2* out = sel ? g_fot : g_kot;
    const int R = sel ? NR : NKO;
    __shared__ __align__(16) float2 tile[32][33];
    int c0 = blockIdx.x * 32, r0 = blockIdx.y * 32;
#pragma unroll
    for (int j = 0; j < 4; ++j) {
        int r = r0 + threadIdx.y + j * 8;
        tile[threadIdx.y + j * 8][threadIdx.x] = in[(size_t)r * NLM + c0 + threadIdx.x];
    }
    __syncthreads();
#pragma unroll
    for (int j = 0; j < 4; ++j) {
        int c = c0 + threadIdx.y + j * 8;
        out[(size_t)c * R + r0 + threadIdx.x] = tile[threadIdx.x][threadIdx.y + j * 8];
    }
}

// ---------------------------------------------------------------------------
// Final projection per k: stage[k][j] = Re( sum_c F[b,c] * W[o,c] ), j=b*64+o.
// ---------------------------------------------------------------------------
__global__ __launch_bounds__(256) void out_gemm() {
    __shared__ __align__(16) float2 Fsh[64 * 33];   // [c][b]
    __shared__ float Osh[64][33];                   // [o][b]
    int k = blockIdx.x;
    for (int j = threadIdx.x; j < NR; j += 256) {
        float2 v = g_fot[(size_t)k * NR + j];
        int bb = j >> 6, cc = j & 63;
        Fsh[cc * 33 + bb] = v;
    }
    __syncthreads();
    int w = threadIdx.x >> 5;
    int b = threadIdx.x & 31;
    const float2* W = g_kot + (size_t)k * NKO;
    float re[8];
#pragma unroll
    for (int i = 0; i < 8; ++i) re[i] = 0.f;
#pragma unroll 4
    for (int c = 0; c < 64; ++c) {
        float2 F = Fsh[c * 33 + b];
#pragma unroll
        for (int i = 0; i < 8; ++i) {
            float2 ww = W[(w + i * 8) * 64 + c];
            re[i] += F.x * ww.x - F.y * ww.y;
        }
    }
#pragma unroll
    for (int i = 0; i < 8; ++i) Osh[w + i * 8][b] = re[i];
    __syncthreads();
    float* st = g_OS + (size_t)k * NR;
    for (int j = threadIdx.x; j < NR; j += 256)
        st[j] = Osh[j & 63][j >> 6];
}

// Float transpose g_OS[1024][2048] -> g_OST[2048][1024]
__global__ void transpose_f() {
    __shared__ float tile[32][33];
    int j0 = blockIdx.x * 32, k0 = blockIdx.y * 32;
#pragma unroll
    for (int jj = 0; jj < 4; ++jj) {
        int k = k0 + threadIdx.y + jj * 8;
        tile[threadIdx.y + jj * 8][threadIdx.x] = g_OS[(size_t)k * NR + j0 + threadIdx.x];
    }
    __syncthreads();
#pragma unroll
    for (int jj = 0; jj < 4; ++jj) {
        int j = j0 + threadIdx.y + jj * 8;
        g_OST[(size_t)j * NLM + k0 + threadIdx.x] = tile[threadIdx.x][threadIdx.y + jj * 8];
    }
}

// Coalesced row write: out[j][s] = (kinv[s] >= 0) ? stage[j][kinv[s]] : 0
__global__ __launch_bounds__(256) void row_write(float* __restrict__ out) {
    int j = blockIdx.x;
    const float* st = g_OST + (size_t)j * NLM;
    float* row = out + (size_t)j * SL;
    for (int s = threadIdx.x; s < SL; s += 256) {
        int kv = g_kinv[s];
        row[s] = (kv >= 0) ? st[kv] : 0.f;
    }
}

// ---------------------------------------------------------------------------
extern "C" void kernel_launch(void* const* d_in, const int* in_sizes, int n_in,
                              void* d_out, int out_size) {
    const float* f_in = (const float*)d_in[0];
    const float* kq   = (const float*)d_in[1];
    const float* kk   = (const float*)d_in[2];
    const float* kv   = (const float*)d_in[3];
    const float* ko   = (const float*)d_in[4];
    const float* Ym   = (const float*)d_in[5];
    const float* Yp   = (const float*)d_in[6];
    const int*   idx  = (const int*)d_in[7];
    float* out = (float*)d_out;

    build_tables<<<128, 256>>>(Ym, Yp, idx, in_sizes[7]);
    build_inv<<<4, 256>>>();
    gather_fc<<<(NR * NLM) / 256, 256>>>(f_in, in_sizes[0]);

    wfwd<<<5632, 128>>>(kq, kk, kv, ko);
    transpose_gen<<<dim3(32, 128), dim3(32, 8)>>>(0);   // koc -> kot

    mega<<<NR, 256>>>();
    transpose_gen<<<dim3(32, 64), dim3(32, 8)>>>(1);    // P -> fot

    out_gemm<<<NLM, 256>>>();
    transpose_f<<<dim3(64, 32), dim3(32, 8)>>>();
    row_write<<<NR, 256>>>(out);
}

// round 14
// speedup vs baseline: 1.2439x; 1.0388x over previous
#include <cuda_runtime.h>
#include <math.h>

// ---------------------------------------------------------------------------
// L=32, M=63, SL=2016, nlm=1024, B=32, C=64, H=8, D=8
// Separable SHT (validated R7-R13, rel_err ~7e-7):
//   Ypinv[k, t*63+p] = D[k,t] e^{-i m_k phi_p},  D = Re(Ypinv) at p=0
//   Ymat [t*63+p, k] = C[t,k] e^{+i m_k phi_p},  C = Re(Ymat)  at p=0
// Complex I/O = real part only (astype semantics).
// R14 = R13 + bank-conflict fixes (X and A stride 64 -> 65).
// ---------------------------------------------------------------------------
#define SL    2016
#define NPHI  63
#define NLM   1024
#define NR    2048
#define NKR   512
#define NK3   1536
#define NKO   4096
#define NOUT  (32 * 64 * SL)

__device__ float  g_D [32 * NLM];      // forward Legendre D[t][k]
__device__ float  g_C [32 * NLM];      // inverse Legendre C[t][k]
__device__ float  g_Ef[64 * 64];       // twiddles [n=2m+c][p]; p=63 col zero
__device__ int    g_sidx[NLM];         // k -> spatial s
__device__ int    g_kinv[SL];          // s -> k or -1
__device__ float  g_fc [NR * NLM];     // gathered f at idx positions
__device__ float2 g_kqkv[NK3 * NLM];   // spectral q|k|v kernels [row][k]
__device__ float2 g_koc [NKO * NLM];   // spectral output kernel [row][k]
__device__ float2 g_kot [NLM * NKO];   // transposed [k][row]
__device__ float2 g_P   [NR * NLM];    // FV * FA [r][k]
__device__ float2 g_fot [NLM * NR];    // transposed [k][r]
__device__ float  g_OS  [(size_t)NLM * NR];   // out stage [k][j]
__device__ float  g_OST [(size_t)NR * NLM];   // out stage [j][k]

__device__ __forceinline__ int iclamp(int i, int n) {
    return (i < 0) ? 0 : ((i >= n) ? n - 1 : i);
}
__device__ __forceinline__ int isqrt_dev(int k) {
    int l = (int)sqrtf((float)k);
    while ((l + 1) * (l + 1) <= k) ++l;
    while (l * l > k) --l;
    return l;
}

// ---------------------------------------------------------------------------
__global__ void build_tables(const float* __restrict__ Ym, const float* __restrict__ Yp,
                             const int* __restrict__ idx, int ni) {
    int i = blockIdx.x * 256 + threadIdx.x;
    if (i < 32 * NLM) {
        int t = i >> 10, k = i & 1023;
        g_D[i] = Yp[(size_t)k * SL + t * NPHI];
        g_C[i] = Ym[(size_t)t * NPHI * NLM + k];
    }
    if (i < 64 * 64) {
        int n = i >> 6, p = i & 63;
        float v = 0.f;
        if (p < NPHI) {
            int m = n >> 1;
            int q = (m * p) % NPHI;
            float ang = 6.283185307179586f * (float)q / (float)NPHI;
            v = (n & 1) ? -sinf(ang) : cosf(ang);
        }
        g_Ef[i] = v;
    }
    if (i < NLM) g_sidx[i] = iclamp(idx[iclamp(i, ni)], SL);
    if (i < SL)  g_kinv[i] = -1;
}

__global__ void build_inv() {
    int k = blockIdx.x * 256 + threadIdx.x;
    if (k < NLM) g_kinv[g_sidx[k]] = k;
}

__global__ void gather_fc(const float* __restrict__ f_in, int nf) {
    int i = blockIdx.x * blockDim.x + threadIdx.x;
    if (i >= NR * NLM) return;
    int r = i >> 10, k = i & (NLM - 1);
    g_fc[i] = f_in[iclamp(r * SL + g_sidx[k], nf)];
}

// ---------------------------------------------------------------------------
// Forward SHT of weights: one block per row (5632), 128 threads.
// X padded to stride 65 (conflict-free column reads in the DFT).
// ---------------------------------------------------------------------------
__global__ __launch_bounds__(128) void wfwd(const float* __restrict__ kq,
                                            const float* __restrict__ kk,
                                            const float* __restrict__ kv,
                                            const float* __restrict__ ko) {
    int r = blockIdx.x;
    const float* src; int row; float2* out; int outr;
    if (r < 512)       { src = kq; row = r;        out = g_kqkv; outr = r; }
    else if (r < 1024) { src = kk; row = r - 512;  out = g_kqkv; outr = r; }
    else if (r < 1536) { src = kv; row = r - 1024; out = g_kqkv; outr = r; }
    else               { src = ko; row = r - 1536; out = g_koc;  outr = r - 1536; }

    __shared__ float Ef[64][65];
    __shared__ float X [32][65];      // stride 65: bank = (t + p) % 32
    __shared__ float Z [32][65];
    const int tid = threadIdx.x;

    for (int i = tid; i < 64 * 64; i += 128) Ef[i >> 6][i & 63] = g_Ef[i];
    for (int i = tid; i < 32 * 63; i += 128) {
        int t = i / 63, p = i - t * 63;
        X[t][p] = src[(size_t)row * SL + i];
    }
    __syncthreads();

    // Z[t][c] = sum_p X[t][p] * Ef[c][p]   (4x4 tiles, 8x16 groups)
    {
        const int tg = tid >> 4, cg = tid & 15;
        float acc[4][4];
#pragma unroll
        for (int i = 0; i < 4; ++i)
#pragma unroll
            for (int j = 0; j < 4; ++j) acc[i][j] = 0.f;
#pragma unroll 7
        for (int p = 0; p < 63; ++p) {
            float xv[4], ev[4];
#pragma unroll
            for (int i = 0; i < 4; ++i) xv[i] = X[tg * 4 + i][p];
#pragma unroll
            for (int j = 0; j < 4; ++j) ev[j] = Ef[cg * 4 + j][p];
#pragma unroll
            for (int i = 0; i < 4; ++i)
#pragma unroll
                for (int j = 0; j < 4; ++j) acc[i][j] += xv[i] * ev[j];
        }
#pragma unroll
        for (int i = 0; i < 4; ++i)
#pragma unroll
            for (int j = 0; j < 4; ++j) Z[tg * 4 + i][cg * 4 + j] = acc[i][j];
    }
    __syncthreads();

    // Legendre: out[k] = sum_t D[t][k] * Z[t][2am(,+1)]
    for (int k = tid; k < NLM; k += 128) {
        int l = isqrt_dev(k);
        int m = k - l * l - l;
        int am = (m < 0) ? -m : m;
        float re = 0.f, im = 0.f;
#pragma unroll 8
        for (int t = 0; t < 32; ++t) {
            float dd = g_D[t * NLM + k];
            re += dd * Z[t][2 * am];
            im += dd * Z[t][2 * am + 1];
        }
        if (m < 0) im = -im;
        out[(size_t)outr * NLM + k] = make_float2(re, im);
    }
}

// ---------------------------------------------------------------------------
// MEGA: per attention-row r (2048 blocks). A gets stride 65 (aliased on Gb,
// which is dead after the inverse Legendre) -> conflict-free DFT phases.
// ---------------------------------------------------------------------------
__global__ __launch_bounds__(256) void mega() {
    const int r = blockIdx.x;
    const int b = r >> 6, ch = r & 63, h = ch >> 3, d = ch & 7;

    __shared__ float  Ef[64][65];
    __shared__ __align__(16) float GbA[32 * 65 + 32];  // Gb (2048 fl) / A[32][65]
    __shared__ float  U [32][65];
    __shared__ float  red[32];
    const int tid = threadIdx.x;
    float2* Gb = reinterpret_cast<float2*>(GbA);
    float*  A  = GbA;                 // stride 65 after Gb is dead

    for (int i = tid; i < 64 * 64; i += 256) Ef[i >> 6][i & 63] = g_Ef[i];

    // ---- qkv head mixing: G to smem, FV to registers ----------------------
    float2 fv[4];
#pragma unroll
    for (int i = 0; i < 4; ++i) {
        int k = tid + i * 256;
        float qr = 0, qi = 0, kr = 0, ki = 0, vr = 0, vi = 0;
#pragma unroll
        for (int c = 0; c < 8; ++c) {
            float f = g_fc[(size_t)((b << 6) + (h << 3) + c) * NLM + k];
            int row = ((h << 3) + c) * 8 + d;
            float2 wq = g_kqkv[(size_t)row * NLM + k];
            float2 wk = g_kqkv[(size_t)(row + NKR) * NLM + k];
            float2 wv = g_kqkv[(size_t)(row + 2 * NKR) * NLM + k];
            qr += f * wq.x; qi += f * wq.y;
            kr += f * wk.x; ki += f * wk.y;
            vr += f * wv.x; vi += f * wv.y;
        }
        Gb[k] = make_float2(qr * kr + qi * ki, qi * kr - qr * ki);
        fv[i] = make_float2(vr, vi);
    }
    __syncthreads();

    // ---- folded inverse Legendre (reads Gb, writes U) ----------------------
    for (int it = tid; it < 1024; it += 256) {
        int t = it >> 5, m = it & 31;
        float ur, ui;
        if (m == 0) {
            float re = 0.f;
            for (int l = 0; l < 32; ++l) {
                int k = l * l + l;
                re += g_C[t * NLM + k] * Gb[k].x;
            }
            ur = re; ui = 0.f;
        } else {
            float rp = 0.f, ip = 0.f, rm = 0.f, im2 = 0.f;
            for (int l = m; l < 32; ++l) {
                int kb = l * l + l;
                float cp = g_C[t * NLM + kb + m];
                float cm = g_C[t * NLM + kb - m];
                float2 gp = Gb[kb + m];
                float2 gm = Gb[kb - m];
                rp += cp * gp.x; ip += cp * gp.y;
                rm += cm * gm.x; im2 += cm * gm.y;
            }
            ur = rp + rm; ui = ip - im2;
        }
        U[t][2 * m]     = ur;
        U[t][2 * m + 1] = ui;
    }
    __syncthreads();   // Gb dead from here; A (stride 65) takes over the buffer

    // ---- inverse phi-DFT: A[t][p] = sum_c U[t][c] * Ef[c][p] --------------
    {
        const int tg = tid >> 4, pg = tid & 15;
        float acc[2][4];
#pragma unroll
        for (int i = 0; i < 2; ++i)
#pragma unroll
            for (int j = 0; j < 4; ++j) acc[i][j] = 0.f;
#pragma unroll 8
        for (int c = 0; c < 64; ++c) {
            float u0 = U[tg * 2][c], u1 = U[tg * 2 + 1][c];
            float ev[4];
#pragma unroll
            for (int j = 0; j < 4; ++j) ev[j] = Ef[c][pg * 4 + j];
#pragma unroll
            for (int j = 0; j < 4; ++j) {
                acc[0][j] += u0 * ev[j];
                acc[1][j] += u1 * ev[j];
            }
        }
#pragma unroll
        for (int i = 0; i < 2; ++i)
#pragma unroll
            for (int j = 0; j < 4; ++j) A[(tg * 2 + i) * 65 + pg * 4 + j] = acc[i][j];
    }
    __syncthreads();
    if (tid < 32) { A[tid * 65 + 63] = -1e30f; A[tid * 65 + 64] = -1e30f; }
    __syncthreads();

    // ---- softmax over 32*65 slots (pads -> exp 0) --------------------------
    {
        float m = -1e30f;
        for (int i = tid; i < 2080; i += 256) m = fmaxf(m, A[i]);
#pragma unroll
        for (int o = 16; o; o >>= 1) m = fmaxf(m, __shfl_xor_sync(0xffffffffu, m, o));
        if ((tid & 31) == 0) red[tid >> 5] = m;
        __syncthreads();
        if (tid < 32) {
            float v = (tid < 8) ? red[tid] : -1e30f;
#pragma unroll
            for (int o = 4; o; o >>= 1) v = fmaxf(v, __shfl_xor_sync(0xffffffffu, v, o));
            if (tid == 0) red[0] = v;
        }
        __syncthreads();
        m = red[0];
        __syncthreads();
        float s = 0.f;
        for (int i = tid; i < 2080; i += 256) {
            float e = __expf(A[i] - m);
            A[i] = e;
            s += e;
        }
#pragma unroll
        for (int o = 16; o; o >>= 1) s += __shfl_xor_sync(0xffffffffu, s, o);
        if ((tid & 31) == 0) red[tid >> 5] = s;
        __syncthreads();
        if (tid < 32) {
            float v = (tid < 8) ? red[tid] : 0.f;
#pragma unroll
            for (int o = 4; o; o >>= 1) v += __shfl_xor_sync(0xffffffffu, v, o);
            if (tid == 0) red[0] = v;
        }
        __syncthreads();
        float inv = 1.0f / red[0];
        for (int i = tid; i < 2080; i += 256) A[i] *= inv;
    }
    __syncthreads();

    // ---- forward phi-DFT: U[t][c] = sum_p A[t][p] * Ef[c][p] --------------
    {
        const int tg = tid >> 4, cg = tid & 15;
        float acc[2][4];
#pragma unroll
        for (int i = 0; i < 2; ++i)
#pragma unroll
            for (int j = 0; j < 4; ++j) acc[i][j] = 0.f;
#pragma unroll 7
        for (int p = 0; p < 63; ++p) {
            float a0 = A[(tg * 2) * 65 + p], a1 = A[(tg * 2 + 1) * 65 + p];
            float ev[4];
#pragma unroll
            for (int j = 0; j < 4; ++j) ev[j] = Ef[cg * 4 + j][p];
#pragma unroll
            for (int j = 0; j < 4; ++j) {
                acc[0][j] += a0 * ev[j];
                acc[1][j] += a1 * ev[j];
            }
        }
#pragma unroll
        for (int i = 0; i < 2; ++i)
#pragma unroll
            for (int j = 0; j < 4; ++j) U[tg * 2 + i][cg * 4 + j] = acc[i][j];
    }
    __syncthreads();

    // ---- forward Legendre + FV*FA ------------------------------------------
#pragma unroll
    for (int i = 0; i < 4; ++i) {
        int k = tid + i * 256;
        int l = isqrt_dev(k);
        int m = k - l * l - l;
        int am = (m < 0) ? -m : m;
        float re = 0.f, im = 0.f;
#pragma unroll 8
        for (int t = 0; t < 32; ++t) {
            float dd = g_D[t * NLM + k];
            re += dd * U[t][2 * am];
            im += dd * U[t][2 * am + 1];
        }
        if (m < 0) im = -im;
        g_P[(size_t)r * NLM + k] =
            make_float2(fv[i].x * re - fv[i].y * im, fv[i].x * im + fv[i].y * re);
    }
}

// ---------------------------------------------------------------------------
__global__ void transpose_gen(int sel) {
    const float2* in = sel ? g_P : g_koc;
    float2* out = sel ? g_fot : g_kot;
    const int R = sel ? NR : NKO;
    __shared__ __align__(16) float2 tile[32][33];
    int c0 = blockIdx.x * 32, r0 = blockIdx.y * 32;
#pragma unroll
    for (int j = 0; j < 4; ++j) {
        int r = r0 + threadIdx.y + j * 8;
        tile[threadIdx.y + j * 8][threadIdx.x] = in[(size_t)r * NLM + c0 + threadIdx.x];
    }
    __syncthreads();
#pragma unroll
    for (int j = 0; j < 4; ++j) {
        int c = c0 + threadIdx.y + j * 8;
        out[(size_t)c * R + r0 + threadIdx.x] = tile[threadIdx.x][threadIdx.y + j * 8];
    }
}

// ---------------------------------------------------------------------------
// Final projection per k: stage[k][j] = Re( sum_c F[b,c] * W[o,c] ), j=b*64+o.
// ---------------------------------------------------------------------------
__global__ __launch_bounds__(256) void out_gemm() {
    __shared__ __align__(16) float2 Fsh[64 * 33];   // [c][b]
    __shared__ float Osh[64][33];                   // [o][b]
    int k = blockIdx.x;
    for (int j = threadIdx.x; j < NR; j += 256) {
        float2 v = g_fot[(size_t)k * NR + j];
        int bb = j >> 6, cc = j & 63;
        Fsh[cc * 33 + bb] = v;
    }
    __syncthreads();
    int w = threadIdx.x >> 5;
    int b = threadIdx.x & 31;
    const float2* W = g_kot + (size_t)k * NKO;
    float re[8];
#pragma unroll
    for (int i = 0; i < 8; ++i) re[i] = 0.f;
#pragma unroll 4
    for (int c = 0; c < 64; ++c) {
        float2 F = Fsh[c * 33 + b];
#pragma unroll
        for (int i = 0; i < 8; ++i) {
            float2 ww = W[(w + i * 8) * 64 + c];
            re[i] += F.x * ww.x - F.y * ww.y;
        }
    }
#pragma unroll
    for (int i = 0; i < 8; ++i) Osh[w + i * 8][b] = re[i];
    __syncthreads();
    float* st = g_OS + (size_t)k * NR;
    for (int j = threadIdx.x; j < NR; j += 256)
        st[j] = Osh[j & 63][j >> 6];
}

// Float transpose g_OS[1024][2048] -> g_OST[2048][1024]
__global__ void transpose_f() {
    __shared__ float tile[32][33];
    int j0 = blockIdx.x * 32, k0 = blockIdx.y * 32;
#pragma unroll
    for (int jj = 0; jj < 4; ++jj) {
        int k = k0 + threadIdx.y + jj * 8;
        tile[threadIdx.y + jj * 8][threadIdx.x] = g_OS[(size_t)k * NR + j0 + threadIdx.x];
    }
    __syncthreads();
#pragma unroll
    for (int jj = 0; jj < 4; ++jj) {
        int j = j0 + threadIdx.y + jj * 8;
        g_OST[(size_t)j * NLM + k0 + threadIdx.x] = tile[threadIdx.x][threadIdx.y + jj * 8];
    }
}

// Coalesced row write: out[j][s] = (kinv[s] >= 0) ? stage[j][kinv[s]] : 0
__global__ __launch_bounds__(256) void row_write(float* __restrict__ out) {
    int j = blockIdx.x;
    const float* st = g_OST + (size_t)j * NLM;
    float* row = out + (size_t)j * SL;
    for (int s = threadIdx.x; s < SL; s += 256) {
        int kv = g_kinv[s];
        row[s] = (kv >= 0) ? st[kv] : 0.f;
    }
}

// ---------------------------------------------------------------------------
extern "C" void kernel_launch(void* const* d_in, const int* in_sizes, int n_in,
                              void* d_out, int out_size) {
    const float* f_in = (const float*)d_in[0];
    const float* kq   = (const float*)d_in[1];
    const float* kk   = (const float*)d_in[2];
    const float* kv   = (const float*)d_in[3];
    const float* ko   = (const float*)d_in[4];
    const float* Ym   = (const float*)d_in[5];
    const float* Yp   = (const float*)d_in[6];
    const int*   idx  = (const int*)d_in[7];
    float* out = (float*)d_out;

    build_tables<<<128, 256>>>(Ym, Yp, idx, in_sizes[7]);
    build_inv<<<4, 256>>>();
    gather_fc<<<(NR * NLM) / 256, 256>>>(f_in, in_sizes[0]);

    wfwd<<<5632, 128>>>(kq, kk, kv, ko);
    transpose_gen<<<dim3(32, 128), dim3(32, 8)>>>(0);   // koc -> kot

    mega<<<NR, 256>>>();
    transpose_gen<<<dim3(32, 64), dim3(32, 8)>>>(1);    // P -> fot

    out_gemm<<<NLM, 256>>>();
    transpose_f<<<dim3(64, 32), dim3(32, 8)>>>();
    row_write<<<NR, 256>>>(out);
}

// round 15
// speedup vs baseline: 1.6050x; 1.2904x over previous
#include <cuda_runtime.h>
#include <math.h>

// ---------------------------------------------------------------------------
// L=32, M=63, SL=2016, nlm=1024, B=32, C=64, H=8, D=8
// Separable SHT (validated R7-R14, rel_err ~7e-7):
//   Ypinv[k, t*63+p] = D[k,t] e^{-i m_k phi_p},  D = Re(Ypinv) at p=0
//   Ymat [t*63+p, k] = C[t,k] e^{+i m_k phi_p},  C = Re(Ymat)  at p=0
// Complex I/O = real part only (astype semantics).
// R15 = R14 + folded (real-signal) phi-DFTs: cos/sin half-tables, q=0..31.
// ---------------------------------------------------------------------------
#define SL    2016
#define NPHI  63
#define NLM   1024
#define NR    2048
#define NKR   512
#define NK3   1536
#define NKO   4096
#define NOUT  (32 * 64 * SL)

__device__ float  g_D [32 * NLM];      // forward Legendre D[t][k]
__device__ float  g_C [32 * NLM];      // inverse Legendre C[t][k]
__device__ float  g_Co[32 * 32];       // cos(m phi_q), m,q = 0..31
__device__ float  g_Si[32 * 32];       // sin(m phi_q)
__device__ int    g_sidx[NLM];         // k -> spatial s
__device__ int    g_kinv[SL];          // s -> k or -1
__device__ float  g_fc [NR * NLM];     // gathered f at idx positions
__device__ float2 g_kqkv[NK3 * NLM];   // spectral q|k|v kernels [row][k]
__device__ float2 g_koc [NKO * NLM];   // spectral output kernel [row][k]
__device__ float2 g_kot [NLM * NKO];   // transposed [k][row]
__device__ float2 g_P   [NR * NLM];    // FV * FA [r][k]
__device__ float2 g_fot [NLM * NR];    // transposed [k][r]
__device__ float  g_OS  [(size_t)NLM * NR];   // out stage [k][j]
__device__ float  g_OST [(size_t)NR * NLM];   // out stage [j][k]

__device__ __forceinline__ int iclamp(int i, int n) {
    return (i < 0) ? 0 : ((i >= n) ? n - 1 : i);
}
__device__ __forceinline__ int isqrt_dev(int k) {
    int l = (int)sqrtf((float)k);
    while ((l + 1) * (l + 1) <= k) ++l;
    while (l * l > k) --l;
    return l;
}

// ---------------------------------------------------------------------------
__global__ void build_tables(const float* __restrict__ Ym, const float* __restrict__ Yp,
                             const int* __restrict__ idx, int ni) {
    int i = blockIdx.x * 256 + threadIdx.x;
    if (i < 32 * NLM) {
        int t = i >> 10, k = i & 1023;
        g_D[i] = Yp[(size_t)k * SL + t * NPHI];
        g_C[i] = Ym[(size_t)t * NPHI * NLM + k];
    }
    if (i < 1024) {
        int m = i >> 5, q = i & 31;
        int qq = (m * q) % NPHI;
        float ang = 6.283185307179586f * (float)qq / (float)NPHI;
        g_Co[i] = cosf(ang);
        g_Si[i] = sinf(ang);
    }
    if (i < NLM) g_sidx[i] = iclamp(idx[iclamp(i, ni)], SL);
    if (i < SL)  g_kinv[i] = -1;
}

__global__ void build_inv() {
    int k = blockIdx.x * 256 + threadIdx.x;
    if (k < NLM) g_kinv[g_sidx[k]] = k;
}

__global__ void gather_fc(const float* __restrict__ f_in, int nf) {
    int i = blockIdx.x * blockDim.x + threadIdx.x;
    if (i >= NR * NLM) return;
    int r = i >> 10, k = i & (NLM - 1);
    g_fc[i] = f_in[iclamp(r * SL + g_sidx[k], nf)];
}

// ---------------------------------------------------------------------------
// Forward SHT of weights: one block per row (5632), 128 threads.
// Folded phi-DFT (q=0..31 sums/diffs) + Legendre.
// ---------------------------------------------------------------------------
__global__ __launch_bounds__(128) void wfwd(const float* __restrict__ kq,
                                            const float* __restrict__ kk,
                                            const float* __restrict__ kv,
                                            const float* __restrict__ ko) {
    int r = blockIdx.x;
    const float* src; int row; float2* out; int outr;
    if (r < 512)       { src = kq; row = r;        out = g_kqkv; outr = r; }
    else if (r < 1024) { src = kk; row = r - 512;  out = g_kqkv; outr = r; }
    else if (r < 1536) { src = kv; row = r - 1024; out = g_kqkv; outr = r; }
    else               { src = ko; row = r - 1536; out = g_koc;  outr = r - 1536; }

    __shared__ float Co[32][33], Si[32][33];
    __shared__ float Xs[32][33], Xd[32][33];
    __shared__ __align__(16) float Z[32][66];
    const int tid = threadIdx.x;

    for (int i = tid; i < 1024; i += 128) {
        int m = i >> 5, q = i & 31;
        Co[m][q] = g_Co[i];
        Si[m][q] = g_Si[i];
    }
    for (int i = tid; i < 1024; i += 128) {
        int t = i >> 5, q = i & 31;
        float a = src[(size_t)row * SL + t * NPHI + q];
        if (q == 0) { Xs[t][0] = a; Xd[t][0] = 0.f; }
        else {
            float bb = src[(size_t)row * SL + t * NPHI + (NPHI - q)];
            Xs[t][q] = a + bb;
            Xd[t][q] = a - bb;
        }
    }
    __syncthreads();

    // Z[t][2m] = sum_q Xs[t][q] Co[m][q];  Z[t][2m+1] = -sum_q Xd[t][q] Si[m][q]
    {
        const int tg = tid >> 4;           // t0 = tg*4
        const int cg = tid & 15;           // m0 = cg*2
        float ar[4][2], ai[4][2];
#pragma unroll
        for (int i = 0; i < 4; ++i)
#pragma unroll
            for (int j = 0; j < 2; ++j) { ar[i][j] = 0.f; ai[i][j] = 0.f; }
#pragma unroll 8
        for (int q = 0; q < 32; ++q) {
            float xs[4], xd[4], co[2], si[2];
#pragma unroll
            for (int i = 0; i < 4; ++i) { xs[i] = Xs[tg * 4 + i][q]; xd[i] = Xd[tg * 4 + i][q]; }
#pragma unroll
            for (int j = 0; j < 2; ++j) { co[j] = Co[cg * 2 + j][q]; si[j] = Si[cg * 2 + j][q]; }
#pragma unroll
            for (int i = 0; i < 4; ++i)
#pragma unroll
                for (int j = 0; j < 2; ++j) {
                    ar[i][j] += xs[i] * co[j];
                    ai[i][j] += xd[i] * si[j];
                }
        }
#pragma unroll
        for (int i = 0; i < 4; ++i)
#pragma unroll
            for (int j = 0; j < 2; ++j) {
                Z[tg * 4 + i][2 * (cg * 2 + j)]     = ar[i][j];
                Z[tg * 4 + i][2 * (cg * 2 + j) + 1] = -ai[i][j];
            }
    }
    __syncthreads();

    // Legendre: out[k] = sum_t D[t][k] * Z[t][2am(,+1)]
    for (int k = tid; k < NLM; k += 128) {
        int l = isqrt_dev(k);
        int m = k - l * l - l;
        int am = (m < 0) ? -m : m;
        float re = 0.f, im = 0.f;
#pragma unroll 8
        for (int t = 0; t < 32; ++t) {
            float dd = g_D[t * NLM + k];
            float2 u = *reinterpret_cast<const float2*>(&Z[t][2 * am]);
            re += dd * u.x;
            im += dd * u.y;
        }
        if (m < 0) im = -im;
        out[(size_t)outr * NLM + k] = make_float2(re, im);
    }
}

// ---------------------------------------------------------------------------
// MEGA: per attention-row r (2048 blocks). Folded DFTs both directions.
// ---------------------------------------------------------------------------
__global__ __launch_bounds__(256) void mega() {
    const int r = blockIdx.x;
    const int b = r >> 6, ch = r & 63, h = ch >> 3, d = ch & 7;

    __shared__ float Co[32][33], Si[32][33];
    __shared__ __align__(16) float GbA[32 * 65 + 32];  // Gb (2048 fl) / A[32][65]
    __shared__ __align__(16) float U[32][66];
    __shared__ float red[32];
    const int tid = threadIdx.x;
    float2* Gb = reinterpret_cast<float2*>(GbA);
    float*  A  = GbA;                 // stride 65 once Gb is dead

    for (int i = tid; i < 1024; i += 256) {
        int m = i >> 5, q = i & 31;
        Co[m][q] = g_Co[i];
        Si[m][q] = g_Si[i];
    }

    // ---- qkv head mixing: G to smem, FV to registers ----------------------
    float2 fv[4];
#pragma unroll
    for (int i = 0; i < 4; ++i) {
        int k = tid + i * 256;
        float qr = 0, qi = 0, kr = 0, ki = 0, vr = 0, vi = 0;
#pragma unroll
        for (int c = 0; c < 8; ++c) {
            float f = g_fc[(size_t)((b << 6) + (h << 3) + c) * NLM + k];
            int row = ((h << 3) + c) * 8 + d;
            float2 wq = g_kqkv[(size_t)row * NLM + k];
            float2 wk = g_kqkv[(size_t)(row + NKR) * NLM + k];
            float2 wv = g_kqkv[(size_t)(row + 2 * NKR) * NLM + k];
            qr += f * wq.x; qi += f * wq.y;
            kr += f * wk.x; ki += f * wk.y;
            vr += f * wv.x; vi += f * wv.y;
        }
        Gb[k] = make_float2(qr * kr + qi * ki, qi * kr - qr * ki);
        fv[i] = make_float2(vr, vi);
    }
    __syncthreads();

    // ---- folded inverse Legendre (reads Gb, writes U) ----------------------
    for (int it = tid; it < 1024; it += 256) {
        int t = it >> 5, m = it & 31;
        float ur, ui;
        if (m == 0) {
            float re = 0.f;
            for (int l = 0; l < 32; ++l) {
                int k = l * l + l;
                re += g_C[t * NLM + k] * Gb[k].x;
            }
            ur = re; ui = 0.f;
        } else {
            float rp = 0.f, ip = 0.f, rm = 0.f, im2 = 0.f;
            for (int l = m; l < 32; ++l) {
                int kb = l * l + l;
                float cp = g_C[t * NLM + kb + m];
                float cm = g_C[t * NLM + kb - m];
                float2 gp = Gb[kb + m];
                float2 gm = Gb[kb - m];
                rp += cp * gp.x; ip += cp * gp.y;
                rm += cm * gm.x; im2 += cm * gm.y;
            }
            ur = rp + rm; ui = ip - im2;
        }
        U[t][2 * m]     = ur;
        U[t][2 * m + 1] = ui;
    }
    __syncthreads();   // Gb dead from here

    // ---- folded inverse phi-DFT: A[q] = Ac-As, A[63-q] = Ac+As -------------
    {
        const int tg = tid >> 4;           // t0 = tg*2
        const int cg = tid & 15;           // q0 = cg*2
        float accC[2][2], accS[2][2];
#pragma unroll
        for (int i = 0; i < 2; ++i)
#pragma unroll
            for (int j = 0; j < 2; ++j) { accC[i][j] = 0.f; accS[i][j] = 0.f; }
#pragma unroll 8
        for (int m = 0; m < 32; ++m) {
            float2 u0 = *reinterpret_cast<const float2*>(&U[tg * 2][2 * m]);
            float2 u1 = *reinterpret_cast<const float2*>(&U[tg * 2 + 1][2 * m]);
            float co[2], si[2];
#pragma unroll
            for (int j = 0; j < 2; ++j) { co[j] = Co[m][cg * 2 + j]; si[j] = Si[m][cg * 2 + j]; }
#pragma unroll
            for (int j = 0; j < 2; ++j) {
                accC[0][j] += u0.x * co[j]; accS[0][j] += u0.y * si[j];
                accC[1][j] += u1.x * co[j]; accS[1][j] += u1.y * si[j];
            }
        }
#pragma unroll
        for (int i = 0; i < 2; ++i)
#pragma unroll
            for (int j = 0; j < 2; ++j) {
                int t = tg * 2 + i, q = cg * 2 + j;
                A[t * 65 + q] = accC[i][j] - accS[i][j];
                if (q) A[t * 65 + (NPHI - q)] = accC[i][j] + accS[i][j];
            }
    }
    __syncthreads();
    if (tid < 32) { A[tid * 65 + 63] = -1e30f; A[tid * 65 + 64] = -1e30f; }
    __syncthreads();

    // ---- softmax over 32*65 slots (pads -> exp 0) --------------------------
    {
        float m = -1e30f;
        for (int i = tid; i < 2080; i += 256) m = fmaxf(m, A[i]);
#pragma unroll
        for (int o = 16; o; o >>= 1) m = fmaxf(m, __shfl_xor_sync(0xffffffffu, m, o));
        if ((tid & 31) == 0) red[tid >> 5] = m;
        __syncthreads();
        if (tid < 32) {
            float v = (tid < 8) ? red[tid] : -1e30f;
#pragma unroll
            for (int o = 4; o; o >>= 1) v = fmaxf(v, __shfl_xor_sync(0xffffffffu, v, o));
            if (tid == 0) red[0] = v;
        }
        __syncthreads();
        m = red[0];
        __syncthreads();
        float s = 0.f;
        for (int i = tid; i < 2080; i += 256) {
            float e = __expf(A[i] - m);
            A[i] = e;
            s += e;
        }
#pragma unroll
        for (int o = 16; o; o >>= 1) s += __shfl_xor_sync(0xffffffffu, s, o);
        if ((tid & 31) == 0) red[tid >> 5] = s;
        __syncthreads();
        if (tid < 32) {
            float v = (tid < 8) ? red[tid] : 0.f;
#pragma unroll
            for (int o = 4; o; o >>= 1) v += __shfl_xor_sync(0xffffffffu, v, o);
            if (tid == 0) red[0] = v;
        }
        __syncthreads();
        float inv = 1.0f / red[0];
        for (int i = tid; i < 2080; i += 256) A[i] *= inv;
    }
    __syncthreads();

    // ---- in-place fold: A[q] <- A[q]+A[63-q], A[63-q] <- A[q]-A[63-q] ------
    for (int i = tid; i < 32 * 31; i += 256) {
        int t = i / 31, q = i - t * 31 + 1;         // q = 1..31
        float a = A[t * 65 + q], bb = A[t * 65 + (NPHI - q)];
        A[t * 65 + q]          = a + bb;
        A[t * 65 + (NPHI - q)] = a - bb;
    }
    __syncthreads();

    // ---- folded forward phi-DFT: U[2m] = sum As*Co, U[2m+1] = -sum Ad*Si ---
    // As at A[t][q] (q=0..31), Ad at A[t][63-q] (q=1..31; q=0 -> A[t][63]=0).
    {
        const int tg = tid >> 4;           // t0 = tg*2
        const int cg = tid & 15;           // m0 = cg*2
        float ar[2][2], ai[2][2];
#pragma unroll
        for (int i = 0; i < 2; ++i)
#pragma unroll
            for (int j = 0; j < 2; ++j) { ar[i][j] = 0.f; ai[i][j] = 0.f; }
#pragma unroll 8
        for (int q = 0; q < 32; ++q) {
            float as0 = A[(tg * 2) * 65 + q],     as1 = A[(tg * 2 + 1) * 65 + q];
            float ad0 = A[(tg * 2) * 65 + (NPHI - q)], ad1 = A[(tg * 2 + 1) * 65 + (NPHI - q)];
            float co[2], si[2];
#pragma unroll
            for (int j = 0; j < 2; ++j) { co[j] = Co[cg * 2 + j][q]; si[j] = Si[cg * 2 + j][q]; }
#pragma unroll
            for (int j = 0; j < 2; ++j) {
                ar[0][j] += as0 * co[j]; ai[0][j] += ad0 * si[j];
                ar[1][j] += as1 * co[j]; ai[1][j] += ad1 * si[j];
            }
        }
#pragma unroll
        for (int i = 0; i < 2; ++i)
#pragma unroll
            for (int j = 0; j < 2; ++j) {
                U[tg * 2 + i][2 * (cg * 2 + j)]     = ar[i][j];
                U[tg * 2 + i][2 * (cg * 2 + j) + 1] = -ai[i][j];
            }
    }
    __syncthreads();

    // ---- forward Legendre + FV*FA ------------------------------------------
#pragma unroll
    for (int i = 0; i < 4; ++i) {
        int k = tid + i * 256;
        int l = isqrt_dev(k);
        int m = k - l * l - l;
        int am = (m < 0) ? -m : m;
        float re = 0.f, im = 0.f;
#pragma unroll 8
        for (int t = 0; t < 32; ++t) {
            float dd = g_D[t * NLM + k];
            float2 u = *reinterpret_cast<const float2*>(&U[t][2 * am]);
            re += dd * u.x;
            im += dd * u.y;
        }
        if (m < 0) im = -im;
        g_P[(size_t)r * NLM + k] =
            make_float2(fv[i].x * re - fv[i].y * im, fv[i].x * im + fv[i].y * re);
    }
}

// ---------------------------------------------------------------------------
__global__ void transpose_gen(int sel) {
    const float2* in = sel ? g_P : g_koc;
    float2* out = sel ? g_fot : g_kot;
    const int R = sel ? NR : NKO;
    __shared__ __align__(16) float2 tile[32][33];
    int c0 = blockIdx.x * 32, r0 = blockIdx.y * 32;
#pragma unroll
    for (int j = 0; j < 4; ++j) {
        int r = r0 + threadIdx.y + j * 8;
        tile[threadIdx.y + j * 8][threadIdx.x] = in[(size_t)r * NLM + c0 + threadIdx.x];
    }
    __syncthreads();
#pragma unroll
    for (int j = 0; j < 4; ++j) {
        int c = c0 + threadIdx.y + j * 8;
        out[(size_t)c * R + r0 + threadIdx.x] = tile[threadIdx.x][threadIdx.y + j * 8];
    }
}

// ---------------------------------------------------------------------------
// Final projection per k: stage[k][j] = Re( sum_c F[b,c] * W[o,c] ), j=b*64+o.
// ---------------------------------------------------------------------------
__global__ __launch_bounds__(256) void out_gemm() {
    __shared__ __align__(16) float2 Fsh[64 * 33];   // [c][b]
    __shared__ float Osh[64][33];                   // [o][b]
    int k = blockIdx.x;
    for (int j = threadIdx.x; j < NR; j += 256) {
        float2 v = g_fot[(size_t)k * NR + j];
        int bb = j >> 6, cc = j & 63;
        Fsh[cc * 33 + bb] = v;
    }
    __syncthreads();
    int w = threadIdx.x >> 5;
    int b = threadIdx.x & 31;
    const float2* W = g_kot + (size_t)k * NKO;
    float re[8];
#pragma unroll
    for (int i = 0; i < 8; ++i) re[i] = 0.f;
#pragma unroll 4
    for (int c = 0; c < 64; ++c) {
        float2 F = Fsh[c * 33 + b];
#pragma unroll
        for (int i = 0; i < 8; ++i) {
            float2 ww = W[(w + i * 8) * 64 + c];
            re[i] += F.x * ww.x - F.y * ww.y;
        }
    }
#pragma unroll
    for (int i = 0; i < 8; ++i) Osh[w + i * 8][b] = re[i];
    __syncthreads();
    float* st = g_OS + (size_t)k * NR;
    for (int j = threadIdx.x; j < NR; j += 256)
        st[j] = Osh[j & 63][j >> 6];
}

// Float transpose g_OS[1024][2048] -> g_OST[2048][1024]
__global__ void transpose_f() {
    __shared__ float tile[32][33];
    int j0 = blockIdx.x * 32, k0 = blockIdx.y * 32;
#pragma unroll
    for (int jj = 0; jj < 4; ++jj) {
        int k = k0 + threadIdx.y + jj * 8;
        tile[threadIdx.y + jj * 8][threadIdx.x] = g_OS[(size_t)k * NR + j0 + threadIdx.x];
    }
    __syncthreads();
#pragma unroll
    for (int jj = 0; jj < 4; ++jj) {
        int j = j0 + threadIdx.y + jj * 8;
        g_OST[(size_t)j * NLM + k0 + threadIdx.x] = tile[threadIdx.x][threadIdx.y + jj * 8];
    }
}

// Coalesced row write: out[j][s] = (kinv[s] >= 0) ? stage[j][kinv[s]] : 0
__global__ __launch_bounds__(256) void row_write(float* __restrict__ out) {
    int j = blockIdx.x;
    const float* st = g_OST + (size_t)j * NLM;
    float* row = out + (size_t)j * SL;
    for (int s = threadIdx.x; s < SL; s += 256) {
        int kv = g_kinv[s];
        row[s] = (kv >= 0) ? st[kv] : 0.f;
    }
}

// ---------------------------------------------------------------------------
extern "C" void kernel_launch(void* const* d_in, const int* in_sizes, int n_in,
                              void* d_out, int out_size) {
    const float* f_in = (const float*)d_in[0];
    const float* kq   = (const float*)d_in[1];
    const float* kk   = (const float*)d_in[2];
    const float* kv   = (const float*)d_in[3];
    const float* ko   = (const float*)d_in[4];
    const float* Ym   = (const float*)d_in[5];
    const float* Yp   = (const float*)d_in[6];
    const int*   idx  = (const int*)d_in[7];
    float* out = (float*)d_out;

    build_tables<<<128, 256>>>(Ym, Yp, idx, in_sizes[7]);
    build_inv<<<4, 256>>>();
    gather_fc<<<(NR * NLM) / 256, 256>>>(f_in, in_sizes[0]);

    wfwd<<<5632, 128>>>(kq, kk, kv, ko);
    transpose_gen<<<dim3(32, 128), dim3(32, 8)>>>(0);   // koc -> kot

    mega<<<NR, 256>>>();
    transpose_gen<<<dim3(32, 64), dim3(32, 8)>>>(1);    // P -> fot

    out_gemm<<<NLM, 256>>>();
    transpose_f<<<dim3(64, 32), dim3(32, 8)>>>();
    row_write<<<NR, 256>>>(out);
}

// round 16
// speedup vs baseline: 1.7086x; 1.0645x over previous
#include <cuda_runtime.h>
#include <math.h>

// ---------------------------------------------------------------------------
// L=32, M=63, SL=2016, nlm=1024, B=32, C=64, H=8, D=8
// Separable SHT (validated R7-R15, rel_err ~7e-7).
// R16 = R15 + row-pair blocking with FUSED table loads:
//   wfwd: rows (2b, 2b+1) share every g_D load.
//   mega: rows (r, r+1024) share q/k/v weight rows and every g_C/g_D load.
// ---------------------------------------------------------------------------
#define SL    2016
#define NPHI  63
#define NLM   1024
#define NR    2048
#define NKR   512
#define NK3   1536
#define NKO   4096
#define NOUT  (32 * 64 * SL)

__device__ float  g_D [32 * NLM];      // forward Legendre D[t][k]
__device__ float  g_C [32 * NLM];      // inverse Legendre C[t][k]
__device__ float  g_Co[32 * 32];       // cos(m phi_q), m,q = 0..31
__device__ float  g_Si[32 * 32];       // sin(m phi_q)
__device__ int    g_sidx[NLM];         // k -> spatial s
__device__ int    g_kinv[SL];          // s -> k or -1
__device__ float  g_fc [NR * NLM];     // gathered f at idx positions
__device__ float2 g_kqkv[NK3 * NLM];   // spectral q|k|v kernels [row][k]
__device__ float2 g_koc [NKO * NLM];   // spectral output kernel [row][k]
__device__ float2 g_kot [NLM * NKO];   // transposed [k][row]
__device__ float2 g_P   [NR * NLM];    // FV * FA [r][k]
__device__ float2 g_fot [NLM * NR];    // transposed [k][r]
__device__ float  g_OS  [(size_t)NLM * NR];   // out stage [k][j]
__device__ float  g_OST [(size_t)NR * NLM];   // out stage [j][k]

__device__ __forceinline__ int iclamp(int i, int n) {
    return (i < 0) ? 0 : ((i >= n) ? n - 1 : i);
}
__device__ __forceinline__ int isqrt_dev(int k) {
    int l = (int)sqrtf((float)k);
    while ((l + 1) * (l + 1) <= k) ++l;
    while (l * l > k) --l;
    return l;
}

// ---------------------------------------------------------------------------
__global__ void build_tables(const float* __restrict__ Ym, const float* __restrict__ Yp,
                             const int* __restrict__ idx, int ni) {
    int i = blockIdx.x * 256 + threadIdx.x;
    if (i < 32 * NLM) {
        int t = i >> 10, k = i & 1023;
        g_D[i] = Yp[(size_t)k * SL + t * NPHI];
        g_C[i] = Ym[(size_t)t * NPHI * NLM + k];
    }
    if (i < 1024) {
        int m = i >> 5, q = i & 31;
        int qq = (m * q) % NPHI;
        float ang = 6.283185307179586f * (float)qq / (float)NPHI;
        g_Co[i] = cosf(ang);
        g_Si[i] = sinf(ang);
    }
    if (i < NLM) g_sidx[i] = iclamp(idx[iclamp(i, ni)], SL);
    if (i < SL)  g_kinv[i] = -1;
}

__global__ void build_inv() {
    int k = blockIdx.x * 256 + threadIdx.x;
    if (k < NLM) g_kinv[g_sidx[k]] = k;
}

__global__ void gather_fc(const float* __restrict__ f_in, int nf) {
    int i = blockIdx.x * blockDim.x + threadIdx.x;
    if (i >= NR * NLM) return;
    int r = i >> 10, k = i & (NLM - 1);
    g_fc[i] = f_in[iclamp(r * SL + g_sidx[k], nf)];
}

// ---------------------------------------------------------------------------
// Forward SHT of weights, 2 rows per block (2816 blocks, 256 threads).
// DFT: half-block per row (parallel). Legendre: fused, one g_D load -> 2 rows.
// ---------------------------------------------------------------------------
__global__ __launch_bounds__(256, 3) void wfwd(const float* __restrict__ kq,
                                               const float* __restrict__ kk,
                                               const float* __restrict__ kv,
                                               const float* __restrict__ ko) {
    const int r0 = blockIdx.x * 2;          // pair (r0, r0+1), same tensor
    const float* src; int row0; float2* outp; int outr0;
    if (r0 < 512)       { src = kq; row0 = r0;        outp = g_kqkv; outr0 = r0; }
    else if (r0 < 1024) { src = kk; row0 = r0 - 512;  outp = g_kqkv; outr0 = r0; }
    else if (r0 < 1536) { src = kv; row0 = r0 - 1024; outp = g_kqkv; outr0 = r0; }
    else                { src = ko; row0 = r0 - 1536; outp = g_koc;  outr0 = r0 - 1536; }

    __shared__ float Co[32][33], Si[32][33];
    __shared__ float Xs[2][32][33], Xd[2][32][33];
    __shared__ __align__(16) float Z[2][32][66];
    const int tid = threadIdx.x;

    for (int i = tid; i < 1024; i += 256) {
        int m = i >> 5, q = i & 31;
        Co[m][q] = g_Co[i];
        Si[m][q] = g_Si[i];
    }
    for (int i = tid; i < 2048; i += 256) {
        int rr = i >> 10;
        int j = i & 1023;
        int t = j >> 5, q = j & 31;
        const float* s = src + (size_t)(row0 + rr) * SL + t * NPHI;
        float a = s[q];
        if (q == 0) { Xs[rr][t][0] = a; Xd[rr][t][0] = 0.f; }
        else {
            float bb = s[NPHI - q];
            Xs[rr][t][q] = a + bb;
            Xd[rr][t][q] = a - bb;
        }
    }
    __syncthreads();

    // folded DFT, half-block per row: Z[2m]=sum Xs*Co, Z[2m+1]=-sum Xd*Si
    {
        const int rr  = tid >> 7;
        const int t2  = tid & 127;
        const int tg  = t2 >> 4;           // t0 = tg*4
        const int cg  = t2 & 15;           // m0 = cg*2
        float ar[4][2], ai[4][2];
#pragma unroll
        for (int i = 0; i < 4; ++i)
#pragma unroll
            for (int j = 0; j < 2; ++j) { ar[i][j] = 0.f; ai[i][j] = 0.f; }
#pragma unroll 8
        for (int q = 0; q < 32; ++q) {
            float xs[4], xd[4], co[2], si[2];
#pragma unroll
            for (int i = 0; i < 4; ++i) { xs[i] = Xs[rr][tg * 4 + i][q]; xd[i] = Xd[rr][tg * 4 + i][q]; }
#pragma unroll
            for (int j = 0; j < 2; ++j) { co[j] = Co[cg * 2 + j][q]; si[j] = Si[cg * 2 + j][q]; }
#pragma unroll
            for (int i = 0; i < 4; ++i)
#pragma unroll
                for (int j = 0; j < 2; ++j) {
                    ar[i][j] += xs[i] * co[j];
                    ai[i][j] += xd[i] * si[j];
                }
        }
#pragma unroll
        for (int i = 0; i < 4; ++i)
#pragma unroll
            for (int j = 0; j < 2; ++j) {
                Z[rr][tg * 4 + i][2 * (cg * 2 + j)]     = ar[i][j];
                Z[rr][tg * 4 + i][2 * (cg * 2 + j) + 1] = -ai[i][j];
            }
    }
    __syncthreads();

    // Legendre, fused: one dd load feeds both rows
    for (int k = tid; k < NLM; k += 256) {
        int l = isqrt_dev(k);
        int m = k - l * l - l;
        int am = (m < 0) ? -m : m;
        float re0 = 0.f, im0 = 0.f, re1 = 0.f, im1 = 0.f;
#pragma unroll 8
        for (int t = 0; t < 32; ++t) {
            float dd = g_D[t * NLM + k];
            float2 u0 = *reinterpret_cast<const float2*>(&Z[0][t][2 * am]);
            float2 u1 = *reinterpret_cast<const float2*>(&Z[1][t][2 * am]);
            re0 += dd * u0.x; im0 += dd * u0.y;
            re1 += dd * u1.x; im1 += dd * u1.y;
        }
        if (m < 0) { im0 = -im0; im1 = -im1; }
        outp[(size_t)outr0 * NLM + k]       = make_float2(re0, im0);
        outp[(size_t)(outr0 + 1) * NLM + k] = make_float2(re1, im1);
    }
}

// ---------------------------------------------------------------------------
// MEGA, 2 rows per block (1024 blocks): rows r0 = bid, r1 = bid + 1024 share
// (h,d) -> identical weights; all table loads fused across the pair.
// ---------------------------------------------------------------------------
__global__ __launch_bounds__(256, 3) void mega() {
    const int bid = blockIdx.x;
    const int ch = bid & 63, h = ch >> 3, d = ch & 7;
    const int b0 = bid >> 6, b1 = b0 + 16;
    const int r0 = bid, r1 = bid + 1024;

    __shared__ float Co[32][33], Si[32][33];
    __shared__ __align__(16) float GbA[2][2112];   // per row: Gb (2048 fl) / A[32][65]
    __shared__ __align__(16) float U[2][32][66];
    __shared__ float red[2][8];
    const int tid = threadIdx.x;
    float2* Gb0 = reinterpret_cast<float2*>(GbA[0]);
    float2* Gb1 = reinterpret_cast<float2*>(GbA[1]);

    for (int i = tid; i < 1024; i += 256) {
        int m = i >> 5, q = i & 31;
        Co[m][q] = g_Co[i];
        Si[m][q] = g_Si[i];
    }

    // ---- qkv head mixing: weights loaded once, applied to both batches ----
    float2 fv0[4], fv1[4];
#pragma unroll
    for (int i = 0; i < 4; ++i) {
        int k = tid + i * 256;
        float qr0 = 0, qi0 = 0, kr0 = 0, ki0 = 0, vr0 = 0, vi0 = 0;
        float qr1 = 0, qi1 = 0, kr1 = 0, ki1 = 0, vr1 = 0, vi1 = 0;
#pragma unroll
        for (int c = 0; c < 8; ++c) {
            int fr = (h << 3) + c;
            float f0 = g_fc[(size_t)((b0 << 6) + fr) * NLM + k];
            float f1 = g_fc[(size_t)((b1 << 6) + fr) * NLM + k];
            int row = fr * 8 + d;
            float2 wq = g_kqkv[(size_t)row * NLM + k];
            float2 wk = g_kqkv[(size_t)(row + NKR) * NLM + k];
            float2 wv = g_kqkv[(size_t)(row + 2 * NKR) * NLM + k];
            qr0 += f0 * wq.x; qi0 += f0 * wq.y; qr1 += f1 * wq.x; qi1 += f1 * wq.y;
            kr0 += f0 * wk.x; ki0 += f0 * wk.y; kr1 += f1 * wk.x; ki1 += f1 * wk.y;
            vr0 += f0 * wv.x; vi0 += f0 * wv.y; vr1 += f1 * wv.x; vi1 += f1 * wv.y;
        }
        Gb0[k] = make_float2(qr0 * kr0 + qi0 * ki0, qi0 * kr0 - qr0 * ki0);
        Gb1[k] = make_float2(qr1 * kr1 + qi1 * ki1, qi1 * kr1 - qr1 * ki1);
        fv0[i] = make_float2(vr0, vi0);
        fv1[i] = make_float2(vr1, vi1);
    }
    __syncthreads();

    // ---- folded inverse Legendre, fused (one C load -> both rows) ----------
    for (int it = tid; it < 1024; it += 256) {
        int t = it >> 5, m = it & 31;
        float ur0, ui0, ur1, ui1;
        if (m == 0) {
            float re0 = 0.f, re1 = 0.f;
            for (int l = 0; l < 32; ++l) {
                int k = l * l + l;
                float cc = g_C[t * NLM + k];
                re0 += cc * Gb0[k].x;
                re1 += cc * Gb1[k].x;
            }
            ur0 = re0; ui0 = 0.f; ur1 = re1; ui1 = 0.f;
        } else {
            float rp0 = 0.f, ip0 = 0.f, rm0 = 0.f, imm0 = 0.f;
            float rp1 = 0.f, ip1 = 0.f, rm1 = 0.f, imm1 = 0.f;
            for (int l = m; l < 32; ++l) {
                int kb = l * l + l;
                float cp = g_C[t * NLM + kb + m];
                float cm = g_C[t * NLM + kb - m];
                float2 gp0 = Gb0[kb + m], gm0 = Gb0[kb - m];
                float2 gp1 = Gb1[kb + m], gm1 = Gb1[kb - m];
                rp0 += cp * gp0.x; ip0 += cp * gp0.y;
                rm0 += cm * gm0.x; imm0 += cm * gm0.y;
                rp1 += cp * gp1.x; ip1 += cp * gp1.y;
                rm1 += cm * gm1.x; imm1 += cm * gm1.y;
            }
            ur0 = rp0 + rm0; ui0 = ip0 - imm0;
            ur1 = rp1 + rm1; ui1 = ip1 - imm1;
        }
        U[0][t][2 * m] = ur0; U[0][t][2 * m + 1] = ui0;
        U[1][t][2 * m] = ur1; U[1][t][2 * m + 1] = ui1;
    }
    __syncthreads();   // Gb dead; A (stride 65) takes over GbA

    const int rr = tid >> 7;        // half-block row id
    const int t2 = tid & 127;
    float* A = GbA[rr];

    // ---- folded inverse phi-DFT (per row on half-block) --------------------
    {
        const int tg = t2 >> 4;            // t0 = tg*4
        const int cg = t2 & 15;            // q0 = cg*2
        float accC[4][2], accS[4][2];
#pragma unroll
        for (int i = 0; i < 4; ++i)
#pragma unroll
            for (int j = 0; j < 2; ++j) { accC[i][j] = 0.f; accS[i][j] = 0.f; }
#pragma unroll 8
        for (int m = 0; m < 32; ++m) {
            float co[2], si[2];
#pragma unroll
            for (int j = 0; j < 2; ++j) { co[j] = Co[m][cg * 2 + j]; si[j] = Si[m][cg * 2 + j]; }
#pragma unroll
            for (int i = 0; i < 4; ++i) {
                float2 u = *reinterpret_cast<const float2*>(&U[rr][tg * 4 + i][2 * m]);
#pragma unroll
                for (int j = 0; j < 2; ++j) {
                    accC[i][j] += u.x * co[j];
                    accS[i][j] += u.y * si[j];
                }
            }
        }
#pragma unroll
        for (int i = 0; i < 4; ++i)
#pragma unroll
            for (int j = 0; j < 2; ++j) {
                int t = tg * 4 + i, q = cg * 2 + j;
                A[t * 65 + q] = accC[i][j] - accS[i][j];
                if (q) A[t * 65 + (NPHI - q)] = accC[i][j] + accS[i][j];
            }
    }
    __syncthreads();
    if (t2 < 32) { A[t2 * 65 + 63] = -1e30f; A[t2 * 65 + 64] = -1e30f; }
    __syncthreads();

    // ---- softmax per row on half-block (128 threads, 4 warps) --------------
    {
        const int wid = t2 >> 5;
        float m = -1e30f;
        for (int i = t2; i < 2080; i += 128) m = fmaxf(m, A[i]);
#pragma unroll
        for (int o = 16; o; o >>= 1) m = fmaxf(m, __shfl_xor_sync(0xffffffffu, m, o));
        if ((t2 & 31) == 0) red[rr][wid] = m;
        __syncthreads();
        m = fmaxf(fmaxf(red[rr][0], red[rr][1]), fmaxf(red[rr][2], red[rr][3]));
        __syncthreads();
        float s = 0.f;
        for (int i = t2; i < 2080; i += 128) {
            float e = __expf(A[i] - m);
            A[i] = e;
            s += e;
        }
#pragma unroll
        for (int o = 16; o; o >>= 1) s += __shfl_xor_sync(0xffffffffu, s, o);
        if ((t2 & 31) == 0) red[rr][wid] = s;
        __syncthreads();
        float inv = 1.0f / (red[rr][0] + red[rr][1] + red[rr][2] + red[rr][3]);
        for (int i = t2; i < 2080; i += 128) A[i] *= inv;
    }
    __syncthreads();

    // ---- in-place fold (per row, half-block) -------------------------------
    for (int i = t2; i < 32 * 31; i += 128) {
        int t = i / 31, q = i - t * 31 + 1;
        float a = A[t * 65 + q], bb = A[t * 65 + (NPHI - q)];
        A[t * 65 + q]          = a + bb;
        A[t * 65 + (NPHI - q)] = a - bb;
    }
    __syncthreads();

    // ---- folded forward phi-DFT (per row, half-block) -----------------------
    {
        const int tg = t2 >> 4;            // t0 = tg*4
        const int cg = t2 & 15;            // m0 = cg*2
        float ar[4][2], ai[4][2];
#pragma unroll
        for (int i = 0; i < 4; ++i)
#pragma unroll
            for (int j = 0; j < 2; ++j) { ar[i][j] = 0.f; ai[i][j] = 0.f; }
#pragma unroll 8
        for (int q = 0; q < 32; ++q) {
            float co[2], si[2];
#pragma unroll
            for (int j = 0; j < 2; ++j) { co[j] = Co[cg * 2 + j][q]; si[j] = Si[cg * 2 + j][q]; }
#pragma unroll
            for (int i = 0; i < 4; ++i) {
                int t = tg * 4 + i;
                float as = A[t * 65 + q];
                float ad = A[t * 65 + (NPHI - q)];   // q=0 -> pad slot (=0 after exp? no)
#pragma unroll
                for (int j = 0; j < 2; ++j) {
                    ar[i][j] += as * co[j];
                    ai[i][j] += ad * si[j];
                }
            }
        }
#pragma unroll
        for (int i = 0; i < 4; ++i)
#pragma unroll
            for (int j = 0; j < 2; ++j) {
                U[rr][tg * 4 + i][2 * (cg * 2 + j)]     = ar[i][j];
                U[rr][tg * 4 + i][2 * (cg * 2 + j) + 1] = -ai[i][j];
            }
    }
    __syncthreads();

    // ---- forward Legendre + FV*FA, fused (one D load -> both rows) ---------
#pragma unroll
    for (int i = 0; i < 4; ++i) {
        int k = tid + i * 256;
        int l = isqrt_dev(k);
        int m = k - l * l - l;
        int am = (m < 0) ? -m : m;
        float re0 = 0.f, im0 = 0.f, re1 = 0.f, im1 = 0.f;
#pragma unroll 8
        for (int t = 0; t < 32; ++t) {
            float dd = g_D[t * NLM + k];
            float2 u0 = *reinterpret_cast<const float2*>(&U[0][t][2 * am]);
            float2 u1 = *reinterpret_cast<const float2*>(&U[1][t][2 * am]);
            re0 += dd * u0.x; im0 += dd * u0.y;
            re1 += dd * u1.x; im1 += dd * u1.y;
        }
        if (m < 0) { im0 = -im0; im1 = -im1; }
        g_P[(size_t)r0 * NLM + k] =
            make_float2(fv0[i].x * re0 - fv0[i].y * im0, fv0[i].x * im0 + fv0[i].y * re0);
        g_P[(size_t)r1 * NLM + k] =
            make_float2(fv1[i].x * re1 - fv1[i].y * im1, fv1[i].x * im1 + fv1[i].y * re1);
    }
}

// ---------------------------------------------------------------------------
__global__ void transpose_gen(int sel) {
    const float2* in = sel ? g_P : g_koc;
    float2* out = sel ? g_fot : g_kot;
    const int R = sel ? NR : NKO;
    __shared__ __align__(16) float2 tile[32][33];
    int c0 = blockIdx.x * 32, r0 = blockIdx.y * 32;
#pragma unroll
    for (int j = 0; j < 4; ++j) {
        int r = r0 + threadIdx.y + j * 8;
        tile[threadIdx.y + j * 8][threadIdx.x] = in[(size_t)r * NLM + c0 + threadIdx.x];
    }
    __syncthreads();
#pragma unroll
    for (int j = 0; j < 4; ++j) {
        int c = c0 + threadIdx.y + j * 8;
        out[(size_t)c * R + r0 + threadIdx.x] = tile[threadIdx.x][threadIdx.y + j * 8];
    }
}

// ---------------------------------------------------------------------------
__global__ __launch_bounds__(256) void out_gemm() {
    __shared__ __align__(16) float2 Fsh[64 * 33];   // [c][b]
    __shared__ float Osh[64][33];                   // [o][b]
    int k = blockIdx.x;
    for (int j = threadIdx.x; j < NR; j += 256) {
        float2 v = g_fot[(size_t)k * NR + j];
        int bb = j >> 6, cc = j & 63;
        Fsh[cc * 33 + bb] = v;
    }
    __syncthreads();
    int w = threadIdx.x >> 5;
    int b = threadIdx.x & 31;
    const float2* W = g_kot + (size_t)k * NKO;
    float re[8];
#pragma unroll
    for (int i = 0; i < 8; ++i) re[i] = 0.f;
#pragma unroll 4
    for (int c = 0; c < 64; ++c) {
        float2 F = Fsh[c * 33 + b];
#pragma unroll
        for (int i = 0; i < 8; ++i) {
            float2 ww = W[(w + i * 8) * 64 + c];
            re[i] += F.x * ww.x - F.y * ww.y;
        }
    }
#pragma unroll
    for (int i = 0; i < 8; ++i) Osh[w + i * 8][b] = re[i];
    __syncthreads();
    float* st = g_OS + (size_t)k * NR;
    for (int j = threadIdx.x; j < NR; j += 256)
        st[j] = Osh[j & 63][j >> 6];
}

__global__ void transpose_f() {
    __shared__ float tile[32][33];
    int j0 = blockIdx.x * 32, k0 = blockIdx.y * 32;
#pragma unroll
    for (int jj = 0; jj < 4; ++jj) {
        int k = k0 + threadIdx.y + jj * 8;
        tile[threadIdx.y + jj * 8][threadIdx.x] = g_OS[(size_t)k * NR + j0 + threadIdx.x];
    }
    __syncthreads();
#pragma unroll
    for (int jj = 0; jj < 4; ++jj) {
        int j = j0 + threadIdx.y + jj * 8;
        g_OST[(size_t)j * NLM + k0 + threadIdx.x] = tile[threadIdx.x][threadIdx.y + jj * 8];
    }
}

__global__ __launch_bounds__(256) void row_write(float* __restrict__ out) {
    int j = blockIdx.x;
    const float* st = g_OST + (size_t)j * NLM;
    float* row = out + (size_t)j * SL;
    for (int s = threadIdx.x; s < SL; s += 256) {
        int kv = g_kinv[s];
        row[s] = (kv >= 0) ? st[kv] : 0.f;
    }
}

// ---------------------------------------------------------------------------
extern "C" void kernel_launch(void* const* d_in, const int* in_sizes, int n_in,
                              void* d_out, int out_size) {
    const float* f_in = (const float*)d_in[0];
    const float* kq   = (const float*)d_in[1];
    const float* kk   = (const float*)d_in[2];
    const float* kv   = (const float*)d_in[3];
    const float* ko   = (const float*)d_in[4];
    const float* Ym   = (const float*)d_in[5];
    const float* Yp   = (const float*)d_in[6];
    const int*   idx  = (const int*)d_in[7];
    float* out = (float*)d_out;

    build_tables<<<128, 256>>>(Ym, Yp, idx, in_sizes[7]);
    build_inv<<<4, 256>>>();
    gather_fc<<<(NR * NLM) / 256, 256>>>(f_in, in_sizes[0]);

    wfwd<<<2816, 256>>>(kq, kk, kv, ko);                // 5632 rows / 2
    transpose_gen<<<dim3(32, 128), dim3(32, 8)>>>(0);   // koc -> kot

    mega<<<1024, 256>>>();                              // 2048 rows / 2
    transpose_gen<<<dim3(32, 64), dim3(32, 8)>>>(1);    // P -> fot

    out_gemm<<<NLM, 256>>>();
    transpose_f<<<dim3(64, 32), dim3(32, 8)>>>();
    row_write<<<NR, 256>>>(out);
}

// round 17
// speedup vs baseline: 1.8896x; 1.1060x over previous
#include <cuda_runtime.h>
#include <math.h>

// ---------------------------------------------------------------------------
// L=32, M=63, SL=2016, nlm=1024, B=32, C=64, H=8, D=8
// Separable SHT (validated R7-R16, rel_err ~7e-7).
// R17 = R16 + conjugate-symmetry halving of forward Legendre phases:
//   flm(l,-m) = (-1)^m conj(flm(l,+m));  D/C[t][k(l,-m)] = (-1)^m D/C[t][k(l,+m)]
// ---------------------------------------------------------------------------
#define SL    2016
#define NPHI  63
#define NLM   1024
#define NR    2048
#define NKR   512
#define NK3   1536
#define NKO   4096
#define NPOS  528              // # of (l,m) with m >= 0
#define NOUT  (32 * 64 * SL)

__device__ float  g_D [32 * NLM];      // forward Legendre D[t][k]
__device__ float  g_C [32 * NLM];      // inverse Legendre C[t][k]
__device__ float  g_Co[32 * 32];       // cos(m phi_q), m,q = 0..31
__device__ float  g_Si[32 * 32];       // sin(m phi_q)
__device__ int    g_jk[NPOS];          // triangular j -> (m<<16)|k(l,+m)
__device__ int    g_sidx[NLM];         // k -> spatial s
__device__ int    g_kinv[SL];          // s -> k or -1
__device__ float  g_fc [NR * NLM];     // gathered f at idx positions
__device__ float2 g_kqkv[NK3 * NLM];   // spectral q|k|v kernels [row][k]
__device__ float2 g_koc [NKO * NLM];   // spectral output kernel [row][k]
__device__ float2 g_kot [NLM * NKO];   // transposed [k][row]
__device__ float2 g_P   [NR * NLM];    // FV * FA [r][k]
__device__ float2 g_fot [NLM * NR];    // transposed [k][r]
__device__ float  g_OS  [(size_t)NLM * NR];   // out stage [k][j]
__device__ float  g_OST [(size_t)NR * NLM];   // out stage [j][k]

__device__ __forceinline__ int iclamp(int i, int n) {
    return (i < 0) ? 0 : ((i >= n) ? n - 1 : i);
}

// ---------------------------------------------------------------------------
__global__ void build_tables(const float* __restrict__ Ym, const float* __restrict__ Yp,
                             const int* __restrict__ idx, int ni) {
    int i = blockIdx.x * 256 + threadIdx.x;
    if (i < 32 * NLM) {
        int t = i >> 10, k = i & 1023;
        g_D[i] = Yp[(size_t)k * SL + t * NPHI];
        g_C[i] = Ym[(size_t)t * NPHI * NLM + k];
    }
    if (i < 1024) {
        int m = i >> 5, q = i & 31;
        int qq = (m * q) % NPHI;
        float ang = 6.283185307179586f * (float)qq / (float)NPHI;
        g_Co[i] = cosf(ang);
        g_Si[i] = sinf(ang);
    }
    if (i < NPOS) {
        int l = (int)((sqrtf(8.f * (float)i + 1.f) - 1.f) * 0.5f);
        while ((l + 1) * (l + 2) / 2 <= i) ++l;
        while (l * (l + 1) / 2 > i) --l;
        int m = i - l * (l + 1) / 2;
        g_jk[i] = (m << 16) | (l * l + l + m);
    }
    if (i < NLM) g_sidx[i] = iclamp(idx[iclamp(i, ni)], SL);
    if (i < SL)  g_kinv[i] = -1;
}

__global__ void build_inv() {
    int k = blockIdx.x * 256 + threadIdx.x;
    if (k < NLM) g_kinv[g_sidx[k]] = k;
}

__global__ void gather_fc(const float* __restrict__ f_in, int nf) {
    int i = blockIdx.x * blockDim.x + threadIdx.x;
    if (i >= NR * NLM) return;
    int r = i >> 10, k = i & (NLM - 1);
    g_fc[i] = f_in[iclamp(r * SL + g_sidx[k], nf)];
}

// ---------------------------------------------------------------------------
// Forward SHT of weights, 2 rows per block (2816 blocks, 256 threads).
// Legendre only over m>=0; negative m mirrored via conjugate symmetry.
// ---------------------------------------------------------------------------
__global__ __launch_bounds__(256, 3) void wfwd(const float* __restrict__ kq,
                                               const float* __restrict__ kk,
                                               const float* __restrict__ kv,
                                               const float* __restrict__ ko) {
    const int r0 = blockIdx.x * 2;          // pair (r0, r0+1), same tensor
    const float* src; int row0; float2* outp; int outr0;
    if (r0 < 512)       { src = kq; row0 = r0;        outp = g_kqkv; outr0 = r0; }
    else if (r0 < 1024) { src = kk; row0 = r0 - 512;  outp = g_kqkv; outr0 = r0; }
    else if (r0 < 1536) { src = kv; row0 = r0 - 1024; outp = g_kqkv; outr0 = r0; }
    else                { src = ko; row0 = r0 - 1536; outp = g_koc;  outr0 = r0 - 1536; }

    __shared__ float Co[32][33], Si[32][33];
    __shared__ float Xs[2][32][33], Xd[2][32][33];
    __shared__ __align__(16) float Z[2][32][66];
    const int tid = threadIdx.x;

    for (int i = tid; i < 1024; i += 256) {
        int m = i >> 5, q = i & 31;
        Co[m][q] = g_Co[i];
        Si[m][q] = g_Si[i];
    }
    for (int i = tid; i < 2048; i += 256) {
        int rr = i >> 10;
        int j = i & 1023;
        int t = j >> 5, q = j & 31;
        const float* s = src + (size_t)(row0 + rr) * SL + t * NPHI;
        float a = s[q];
        if (q == 0) { Xs[rr][t][0] = a; Xd[rr][t][0] = 0.f; }
        else {
            float bb = s[NPHI - q];
            Xs[rr][t][q] = a + bb;
            Xd[rr][t][q] = a - bb;
        }
    }
    __syncthreads();

    // folded DFT, half-block per row: Z[2m]=sum Xs*Co, Z[2m+1]=-sum Xd*Si
    {
        const int rr  = tid >> 7;
        const int t2  = tid & 127;
        const int tg  = t2 >> 4;           // t0 = tg*4
        const int cg  = t2 & 15;           // m0 = cg*2
        float ar[4][2], ai[4][2];
#pragma unroll
        for (int i = 0; i < 4; ++i)
#pragma unroll
            for (int j = 0; j < 2; ++j) { ar[i][j] = 0.f; ai[i][j] = 0.f; }
#pragma unroll 8
        for (int q = 0; q < 32; ++q) {
            float xs[4], xd[4], co[2], si[2];
#pragma unroll
            for (int i = 0; i < 4; ++i) { xs[i] = Xs[rr][tg * 4 + i][q]; xd[i] = Xd[rr][tg * 4 + i][q]; }
#pragma unroll
            for (int j = 0; j < 2; ++j) { co[j] = Co[cg * 2 + j][q]; si[j] = Si[cg * 2 + j][q]; }
#pragma unroll
            for (int i = 0; i < 4; ++i)
#pragma unroll
                for (int j = 0; j < 2; ++j) {
                    ar[i][j] += xs[i] * co[j];
                    ai[i][j] += xd[i] * si[j];
                }
        }
#pragma unroll
        for (int i = 0; i < 4; ++i)
#pragma unroll
            for (int j = 0; j < 2; ++j) {
                Z[rr][tg * 4 + i][2 * (cg * 2 + j)]     = ar[i][j];
                Z[rr][tg * 4 + i][2 * (cg * 2 + j) + 1] = -ai[i][j];
            }
    }
    __syncthreads();

    // Legendre over m>=0 only; mirror negative m: out(-m) = (-1)^m conj(out(+m))
    for (int j = tid; j < NPOS; j += 256) {
        int pk = g_jk[j];
        int m  = pk >> 16;
        int kp = pk & 0xFFFF;
        float re0 = 0.f, im0 = 0.f, re1 = 0.f, im1 = 0.f;
#pragma unroll 8
        for (int t = 0; t < 32; ++t) {
            float dd = g_D[t * NLM + kp];
            float2 u0 = *reinterpret_cast<const float2*>(&Z[0][t][2 * m]);
            float2 u1 = *reinterpret_cast<const float2*>(&Z[1][t][2 * m]);
            re0 += dd * u0.x; im0 += dd * u0.y;
            re1 += dd * u1.x; im1 += dd * u1.y;
        }
        outp[(size_t)outr0 * NLM + kp]       = make_float2(re0, im0);
        outp[(size_t)(outr0 + 1) * NLM + kp] = make_float2(re1, im1);
        if (m) {
            float s = (m & 1) ? -1.f : 1.f;
            int km = kp - 2 * m;
            outp[(size_t)outr0 * NLM + km]       = make_float2(s * re0, -s * im0);
            outp[(size_t)(outr0 + 1) * NLM + km] = make_float2(s * re1, -s * im1);
        }
    }
}

// ---------------------------------------------------------------------------
// MEGA, 2 rows per block (1024 blocks): rows r0 = bid, r1 = bid + 1024 share
// (h,d) -> identical weights; table loads fused; forward Legendre halved.
// ---------------------------------------------------------------------------
__global__ __launch_bounds__(256, 3) void mega() {
    const int bid = blockIdx.x;
    const int ch = bid & 63, h = ch >> 3, d = ch & 7;
    const int b0 = bid >> 6, b1 = b0 + 16;
    const int r0 = bid, r1 = bid + 1024;

    __shared__ float Co[32][33], Si[32][33];
    __shared__ __align__(16) float GbA[2][2112];   // per row: Gb / A[32][65] / FA
    __shared__ __align__(16) float U[2][32][66];
    __shared__ float red[2][8];
    const int tid = threadIdx.x;
    float2* Gb0 = reinterpret_cast<float2*>(GbA[0]);
    float2* Gb1 = reinterpret_cast<float2*>(GbA[1]);

    for (int i = tid; i < 1024; i += 256) {
        int m = i >> 5, q = i & 31;
        Co[m][q] = g_Co[i];
        Si[m][q] = g_Si[i];
    }

    // ---- qkv head mixing: weights loaded once, applied to both batches ----
    float2 fv0[4], fv1[4];
#pragma unroll
    for (int i = 0; i < 4; ++i) {
        int k = tid + i * 256;
        float qr0 = 0, qi0 = 0, kr0 = 0, ki0 = 0, vr0 = 0, vi0 = 0;
        float qr1 = 0, qi1 = 0, kr1 = 0, ki1 = 0, vr1 = 0, vi1 = 0;
#pragma unroll
        for (int c = 0; c < 8; ++c) {
            int fr = (h << 3) + c;
            float f0 = g_fc[(size_t)((b0 << 6) + fr) * NLM + k];
            float f1 = g_fc[(size_t)((b1 << 6) + fr) * NLM + k];
            int row = fr * 8 + d;
            float2 wq = g_kqkv[(size_t)row * NLM + k];
            float2 wk = g_kqkv[(size_t)(row + NKR) * NLM + k];
            float2 wv = g_kqkv[(size_t)(row + 2 * NKR) * NLM + k];
            qr0 += f0 * wq.x; qi0 += f0 * wq.y; qr1 += f1 * wq.x; qi1 += f1 * wq.y;
            kr0 += f0 * wk.x; ki0 += f0 * wk.y; kr1 += f1 * wk.x; ki1 += f1 * wk.y;
            vr0 += f0 * wv.x; vi0 += f0 * wv.y; vr1 += f1 * wv.x; vi1 += f1 * wv.y;
        }
        Gb0[k] = make_float2(qr0 * kr0 + qi0 * ki0, qi0 * kr0 - qr0 * ki0);
        Gb1[k] = make_float2(qr1 * kr1 + qi1 * ki1, qi1 * kr1 - qr1 * ki1);
        fv0[i] = make_float2(vr0, vi0);
        fv1[i] = make_float2(vr1, vi1);
    }
    __syncthreads();

    // ---- folded inverse Legendre, fused; C(-m) = (-1)^m C(+m) (one load) ---
    for (int it = tid; it < 1024; it += 256) {
        int t = it >> 5, m = it & 31;
        float ur0, ui0, ur1, ui1;
        if (m == 0) {
            float re0 = 0.f, re1 = 0.f;
            for (int l = 0; l < 32; ++l) {
                int k = l * l + l;
                float cc = g_C[t * NLM + k];
                re0 += cc * Gb0[k].x;
                re1 += cc * Gb1[k].x;
            }
            ur0 = re0; ui0 = 0.f; ur1 = re1; ui1 = 0.f;
        } else {
            float s = (m & 1) ? -1.f : 1.f;
            ur0 = 0.f; ui0 = 0.f; ur1 = 0.f; ui1 = 0.f;
            for (int l = m; l < 32; ++l) {
                int kb = l * l + l;
                float cp = g_C[t * NLM + kb + m];
                float2 gp0 = Gb0[kb + m], gm0 = Gb0[kb - m];
                float2 gp1 = Gb1[kb + m], gm1 = Gb1[kb - m];
                ur0 += cp * (gp0.x + s * gm0.x);
                ui0 += cp * (gp0.y - s * gm0.y);
                ur1 += cp * (gp1.x + s * gm1.x);
                ui1 += cp * (gp1.y - s * gm1.y);
            }
        }
        U[0][t][2 * m] = ur0; U[0][t][2 * m + 1] = ui0;
        U[1][t][2 * m] = ur1; U[1][t][2 * m + 1] = ui1;
    }
    __syncthreads();   // Gb dead; A (stride 65) takes over GbA

    const int rr = tid >> 7;        // half-block row id
    const int t2 = tid & 127;
    float* A = GbA[rr];

    // ---- folded inverse phi-DFT (per row on half-block) --------------------
    {
        const int tg = t2 >> 4;            // t0 = tg*4
        const int cg = t2 & 15;            // q0 = cg*2
        float accC[4][2], accS[4][2];
#pragma unroll
        for (int i = 0; i < 4; ++i)
#pragma unroll
            for (int j = 0; j < 2; ++j) { accC[i][j] = 0.f; accS[i][j] = 0.f; }
#pragma unroll 8
        for (int m = 0; m < 32; ++m) {
            float co[2], si[2];
#pragma unroll
            for (int j = 0; j < 2; ++j) { co[j] = Co[m][cg * 2 + j]; si[j] = Si[m][cg * 2 + j]; }
#pragma unroll
            for (int i = 0; i < 4; ++i) {
                float2 u = *reinterpret_cast<const float2*>(&U[rr][tg * 4 + i][2 * m]);
#pragma unroll
                for (int j = 0; j < 2; ++j) {
                    accC[i][j] += u.x * co[j];
                    accS[i][j] += u.y * si[j];
                }
            }
        }
#pragma unroll
        for (int i = 0; i < 4; ++i)
#pragma unroll
            for (int j = 0; j < 2; ++j) {
                int t = tg * 4 + i, q = cg * 2 + j;
                A[t * 65 + q] = accC[i][j] - accS[i][j];
                if (q) A[t * 65 + (NPHI - q)] = accC[i][j] + accS[i][j];
            }
    }
    __syncthreads();
    if (t2 < 32) { A[t2 * 65 + 63] = -1e30f; A[t2 * 65 + 64] = -1e30f; }
    __syncthreads();

    // ---- softmax per row on half-block (128 threads, 4 warps) --------------
    {
        const int wid = t2 >> 5;
        float m = -1e30f;
        for (int i = t2; i < 2080; i += 128) m = fmaxf(m, A[i]);
#pragma unroll
        for (int o = 16; o; o >>= 1) m = fmaxf(m, __shfl_xor_sync(0xffffffffu, m, o));
        if ((t2 & 31) == 0) red[rr][wid] = m;
        __syncthreads();
        m = fmaxf(fmaxf(red[rr][0], red[rr][1]), fmaxf(red[rr][2], red[rr][3]));
        __syncthreads();
        float s = 0.f;
        for (int i = t2; i < 2080; i += 128) {
            float e = __expf(A[i] - m);
            A[i] = e;
            s += e;
        }
#pragma unroll
        for (int o = 16; o; o >>= 1) s += __shfl_xor_sync(0xffffffffu, s, o);
        if ((t2 & 31) == 0) red[rr][wid] = s;
        __syncthreads();
        float inv = 1.0f / (red[rr][0] + red[rr][1] + red[rr][2] + red[rr][3]);
        for (int i = t2; i < 2080; i += 128) A[i] *= inv;
    }
    __syncthreads();

    // ---- in-place fold (per row, half-block) -------------------------------
    for (int i = t2; i < 32 * 31; i += 128) {
        int t = i / 31, q = i - t * 31 + 1;
        float a = A[t * 65 + q], bb = A[t * 65 + (NPHI - q)];
        A[t * 65 + q]          = a + bb;
        A[t * 65 + (NPHI - q)] = a - bb;
    }
    __syncthreads();

    // ---- folded forward phi-DFT (per row, half-block) -----------------------
    {
        const int tg = t2 >> 4;            // t0 = tg*4
        const int cg = t2 & 15;            // m0 = cg*2
        float ar[4][2], ai[4][2];
#pragma unroll
        for (int i = 0; i < 4; ++i)
#pragma unroll
            for (int j = 0; j < 2; ++j) { ar[i][j] = 0.f; ai[i][j] = 0.f; }
#pragma unroll 8
        for (int q = 0; q < 32; ++q) {
            float co[2], si[2];
#pragma unroll
            for (int j = 0; j < 2; ++j) { co[j] = Co[cg * 2 + j][q]; si[j] = Si[cg * 2 + j][q]; }
#pragma unroll
            for (int i = 0; i < 4; ++i) {
                int t = tg * 4 + i;
                float as = A[t * 65 + q];
                float ad = A[t * 65 + (NPHI - q)];   // q=0 -> col 63 = 0 after softmax
#pragma unroll
                for (int j = 0; j < 2; ++j) {
                    ar[i][j] += as * co[j];
                    ai[i][j] += ad * si[j];
                }
            }
        }
#pragma unroll
        for (int i = 0; i < 4; ++i)
#pragma unroll
            for (int j = 0; j < 2; ++j) {
                U[rr][tg * 4 + i][2 * (cg * 2 + j)]     = ar[i][j];
                U[rr][tg * 4 + i][2 * (cg * 2 + j) + 1] = -ai[i][j];
            }
    }
    __syncthreads();   // A dead; FA takes over GbA

    // ---- forward Legendre over m>=0, fused; mirror into FA (smem) ----------
    float2* FA0 = reinterpret_cast<float2*>(GbA[0]);
    float2* FA1 = reinterpret_cast<float2*>(GbA[1]);
    for (int j = tid; j < NPOS; j += 256) {
        int pk = g_jk[j];
        int m  = pk >> 16;
        int kp = pk & 0xFFFF;
        float re0 = 0.f, im0 = 0.f, re1 = 0.f, im1 = 0.f;
#pragma unroll 8
        for (int t = 0; t < 32; ++t) {
            float dd = g_D[t * NLM + kp];
            float2 u0 = *reinterpret_cast<const float2*>(&U[0][t][2 * m]);
            float2 u1 = *reinterpret_cast<const float2*>(&U[1][t][2 * m]);
            re0 += dd * u0.x; im0 += dd * u0.y;
            re1 += dd * u1.x; im1 += dd * u1.y;
        }
        FA0[kp] = make_float2(re0, im0);
        FA1[kp] = make_float2(re1, im1);
        if (m) {
            float s = (m & 1) ? -1.f : 1.f;
            int km = kp - 2 * m;
            FA0[km] = make_float2(s * re0, -s * im0);
            FA1[km] = make_float2(s * re1, -s * im1);
        }
    }
    __syncthreads();

    // ---- P = FV * FA (fv in registers, FA from smem) ------------------------
#pragma unroll
    for (int i = 0; i < 4; ++i) {
        int k = tid + i * 256;
        float2 a0 = FA0[k], a1 = FA1[k];
        g_P[(size_t)r0 * NLM + k] =
            make_float2(fv0[i].x * a0.x - fv0[i].y * a0.y, fv0[i].x * a0.y + fv0[i].y * a0.x);
        g_P[(size_t)r1 * NLM + k] =
            make_float2(fv1[i].x * a1.x - fv1[i].y * a1.y, fv1[i].x * a1.y + fv1[i].y * a1.x);
    }
}

// ---------------------------------------------------------------------------
__global__ void transpose_gen(int sel) {
    const float2* in = sel ? g_P : g_koc;
    float2* out = sel ? g_fot : g_kot;
    const int R = sel ? NR : NKO;
    __shared__ __align__(16) float2 tile[32][33];
    int c0 = blockIdx.x * 32, r0 = blockIdx.y * 32;
#pragma unroll
    for (int j = 0; j < 4; ++j) {
        int r = r0 + threadIdx.y + j * 8;
        tile[threadIdx.y + j * 8][threadIdx.x] = in[(size_t)r * NLM + c0 + threadIdx.x];
    }
    __syncthreads();
#pragma unroll
    for (int j = 0; j < 4; ++j) {
        int c = c0 + threadIdx.y + j * 8;
        out[(size_t)c * R + r0 + threadIdx.x] = tile[threadIdx.x][threadIdx.y + j * 8];
    }
}

// ---------------------------------------------------------------------------
__global__ __launch_bounds__(256) void out_gemm() {
    __shared__ __align__(16) float2 Fsh[64 * 33];   // [c][b]
    __shared__ float Osh[64][33];                   // [o][b]
    int k = blockIdx.x;
    for (int j = threadIdx.x; j < NR; j += 256) {
        float2 v = g_fot[(size_t)k * NR + j];
        int bb = j >> 6, cc = j & 63;
        Fsh[cc * 33 + bb] = v;
    }
    __syncthreads();
    int w = threadIdx.x >> 5;
    int b = threadIdx.x & 31;
    const float2* W = g_kot + (size_t)k * NKO;
    float re[8];
#pragma unroll
    for (int i = 0; i < 8; ++i) re[i] = 0.f;
#pragma unroll 4
    for (int c = 0; c < 64; ++c) {
        float2 F = Fsh[c * 33 + b];
#pragma unroll
        for (int i = 0; i < 8; ++i) {
            float2 ww = W[(w + i * 8) * 64 + c];
            re[i] += F.x * ww.x - F.y * ww.y;
        }
    }
#pragma unroll
    for (int i = 0; i < 8; ++i) Osh[w + i * 8][b] = re[i];
    __syncthreads();
    float* st = g_OS + (size_t)k * NR;
    for (int j = threadIdx.x; j < NR; j += 256)
        st[j] = Osh[j & 63][j >> 6];
}

__global__ void transpose_f() {
    __shared__ float tile[32][33];
    int j0 = blockIdx.x * 32, k0 = blockIdx.y * 32;
#pragma unroll
    for (int jj = 0; jj < 4; ++jj) {
        int k = k0 + threadIdx.y + jj * 8;
        tile[threadIdx.y + jj * 8][threadIdx.x] = g_OS[(size_t)k * NR + j0 + threadIdx.x];
    }
    __syncthreads();
#pragma unroll
    for (int jj = 0; jj < 4; ++jj) {
        int j = j0 + threadIdx.y + jj * 8;
        g_OST[(size_t)j * NLM + k0 + threadIdx.x] = tile[threadIdx.x][threadIdx.y + jj * 8];
    }
}

__global__ __launch_bounds__(256) void row_write(float* __restrict__ out) {
    int j = blockIdx.x;
    const float* st = g_OST + (size_t)j * NLM;
    float* row = out + (size_t)j * SL;
    for (int s = threadIdx.x; s < SL; s += 256) {
        int kv = g_kinv[s];
        row[s] = (kv >= 0) ? st[kv] : 0.f;
    }
}

// ---------------------------------------------------------------------------
extern "C" void kernel_launch(void* const* d_in, const int* in_sizes, int n_in,
                              void* d_out, int out_size) {
    const float* f_in = (const float*)d_in[0];
    const float* kq   = (const float*)d_in[1];
    const float* kk   = (const float*)d_in[2];
    const float* kv   = (const float*)d_in[3];
    const float* ko   = (const float*)d_in[4];
    const float* Ym   = (const float*)d_in[5];
    const float* Yp   = (const float*)d_in[6];
    const int*   idx  = (const int*)d_in[7];
    float* out = (float*)d_out;

    build_tables<<<128, 256>>>(Ym, Yp, idx, in_sizes[7]);
    build_inv<<<4, 256>>>();
    gather_fc<<<(NR * NLM) / 256, 256>>>(f_in, in_sizes[0]);

    wfwd<<<2816, 256>>>(kq, kk, kv, ko);                // 5632 rows / 2
    transpose_gen<<<dim3(32, 128), dim3(32, 8)>>>(0);   // koc -> kot

    mega<<<1024, 256>>>();                              // 2048 rows / 2
    transpose_gen<<<dim3(32, 64), dim3(32, 8)>>>(1);    // P -> fot

    out_gemm<<<NLM, 256>>>();
    transpose_f<<<dim3(64, 32), dim3(32, 8)>>>();
    row_write<<<NR, 256>>>(out);
}